// round 14
// baseline (speedup 1.0000x reference)
#include <cuda_runtime.h>
#include <cstdint>

#define BATCH 4
#define SEQ   1024
#define DIM   1024
#define NH    16
#define HD    64

// -------------------- device scratch (allocation-free) ----------------------
__device__ float g_q[BATCH * NH * SEQ * HD];     // head-split, tf32-rounded, pre-scaled 1/8
__device__ float g_k[BATCH * NH * SEQ * HD];
__device__ float g_vt[BATCH * NH * HD * SEQ];    // V proj, transposed [b,h,d,s]
__device__ float g_ctx[BATCH * SEQ * DIM];       // attn output (tf32-rna rounded)
__device__ float g_wqt[DIM * DIM];               // W_q^T rounded, [n][k]
__device__ float g_wot[DIM * DIM];               // W_o^T rounded, [n][k]

// -------------------- helpers ----------------------------------------------
__device__ __forceinline__ uint32_t smem_u32(const void* p) {
    uint32_t a;
    asm("{ .reg .u64 t; cvta.to.shared.u64 t, %1; cvt.u32.u64 %0, t; }" : "=r"(a) : "l"(p));
    return a;
}
__device__ __forceinline__ float f_rna_tf32(float f) {
    uint32_t r; asm("cvt.rna.tf32.f32 %0, %1;" : "=r"(r) : "f"(f));
    return __uint_as_float(r);
}
__device__ __forceinline__ uint32_t rna_bits(uint32_t x) {
    uint32_t r; asm("cvt.rna.tf32.f32 %0, %1;" : "=r"(r) : "f"(__uint_as_float(x)));
    return r;
}

#define CP_ASYNC16(sa, gp) \
    asm volatile("cp.async.cg.shared.global [%0], [%1], 16;" :: "r"(sa), "l"(gp))
#define CP_COMMIT() asm volatile("cp.async.commit_group;" ::: "memory")
#define CP_WAIT(n)  asm volatile("cp.async.wait_group %0;" :: "n"(n) : "memory")

#define LDSM_X4(r0, r1, r2, r3, a) \
    asm volatile("ldmatrix.sync.aligned.m8n8.x4.shared.b16 {%0,%1,%2,%3}, [%4];" \
                 : "=r"(r0), "=r"(r1), "=r"(r2), "=r"(r3) : "r"(a))

__device__ __forceinline__ void mma_tf32(float& d0, float& d1, float& d2, float& d3,
                                         uint32_t a0, uint32_t a1, uint32_t a2, uint32_t a3,
                                         uint32_t b0, uint32_t b1) {
    asm volatile(
        "mma.sync.aligned.m16n8k8.row.col.f32.tf32.tf32.f32 "
        "{%0,%1,%2,%3}, {%4,%5,%6,%7}, {%8,%9}, {%0,%1,%2,%3};"
        : "+f"(d0), "+f"(d1), "+f"(d2), "+f"(d3)
        : "r"(a0), "r"(a1), "r"(a2), "r"(a3), "r"(b0), "r"(b1));
}

// -------------------- prep: transpose + round weights -----------------------
__global__ void prep_wt(const float* __restrict__ Wq, const float* __restrict__ Wo)
{
    const float* src = blockIdx.z ? Wo : Wq;
    float* dst = blockIdx.z ? g_wot : g_wqt;
    __shared__ float t[32][33];
    const int tid = threadIdx.x;
    const int n0 = blockIdx.x * 32, k0 = blockIdx.y * 32;
#pragma unroll
    for (int i = 0; i < 4; i++) {
        int idx = tid + i * 256, r = idx >> 5, c = idx & 31;
        t[r][c] = src[(k0 + r) * DIM + n0 + c];
    }
    __syncthreads();
#pragma unroll
    for (int i = 0; i < 4; i++) {
        int idx = tid + i * 256, r = idx >> 5, c = idx & 31;
        dst[(n0 + r) * DIM + k0 + c] = f_rna_tf32(t[c][r]);
    }
}

// -------------------- GEMM common config (round-12 proven) ------------------
#define PITCH 36
#define AB_BUF (128 * PITCH)
#define GEMM_SMEM_BYTES (6 * AB_BUF * 4)     // 110592
#define KCHUNKS 32
#define VT_PITCH 132
#define NTILES_PROJ 768                      // 8 x 32 x 3
#define NPERSIST 296                         // 2 CTA/SM x 148 SMs

// -------------------- persistent projection GEMM ----------------------------
// 256 thr, 8 warps (2x4), warp tile 64x32 — the measured-best config.
// Each CTA loops tiles bid, bid+296, ... over the 768 proj tiles.
// z=0: Q (x1/8) -> g_q; z=1: K -> g_k; z=2: V -> g_vt (direct transpose).
__global__ __launch_bounds__(256, 2) void gemm_proj_persist(
    const float* __restrict__ A0, const float* __restrict__ A1,
    const float* __restrict__ A2, const int* __restrict__ vlens)
{
    extern __shared__ float sm[];
    const uint32_t sb = smem_u32(sm);
    const int tid = threadIdx.x, lane = tid & 31, wid = tid >> 5;
    const int wm = wid >> 2, wn = wid & 3;

    // tile-invariant staging plan
    uint32_t saA[4], saB[4];
    int stR[4], stC[4];
#pragma unroll
    for (int i = 0; i < 4; i++) {
        int s = tid + i * 256;
        stR[i] = s >> 3; stC[i] = s & 7;
        saA[i] = sb + (stR[i] * PITCH + stC[i] * 4) * 4;
        saB[i] = sb + (3 * AB_BUF + stR[i] * PITCH + stC[i] * 4) * 4;
    }
    const uint32_t laneA = ((lane & 15) * PITCH + ((lane >> 4) << 2)) * 4;
    const uint32_t laneB = (((lane & 7) + ((lane & 16) ? 8 : 0)) * PITCH +
                            ((lane & 8) ? 4 : 0)) * 4;
    uint32_t aBase[4], bBase[2];
#pragma unroll
    for (int mf = 0; mf < 4; mf++) aBase[mf] = (wm * 64 + mf * 16) * PITCH * 4 + laneA;
#pragma unroll
    for (int p = 0; p < 2; p++)
        bBase[p] = 3 * AB_BUF * 4 + (wn * 32 + p * 16) * PITCH * 4 + laneB;
    const int ar = lane >> 2, ac = lane & 3;

#pragma unroll 1
    for (int tile = blockIdx.x; tile < NTILES_PROJ; tile += NPERSIST) {
        const int z = tile >> 8;
        const int rem = tile & 255;
        const int m0 = (rem >> 3) * 128, n0 = (rem & 7) * 128;
        if (z != 0 && (m0 & (SEQ - 1)) >= vlens[m0 >> 10]) continue;

        const float* A = (z == 0) ? A0 : (z == 1) ? A1 : A2;
        float* dst     = (z == 0) ? g_q : (z == 1) ? g_k : g_vt;

        const float* gpA[4]; const float* gpB[4];
#pragma unroll
        for (int i = 0; i < 4; i++) {
            gpA[i] = A + (m0 + stR[i]) * DIM + stC[i] * 4;
            gpB[i] = g_wqt + (n0 + stR[i]) * DIM + stC[i] * 4;
        }

        float acc[4][4][4];
#pragma unroll
        for (int mf = 0; mf < 4; mf++)
#pragma unroll
            for (int nf = 0; nf < 4; nf++)
#pragma unroll
                for (int e = 0; e < 4; e++) acc[mf][nf][e] = 0.f;

        // prologue: chunks 0,1
#pragma unroll
        for (int i = 0; i < 4; i++) CP_ASYNC16(saA[i], gpA[i]);
#pragma unroll
        for (int i = 0; i < 4; i++) CP_ASYNC16(saB[i], gpB[i]);
        CP_COMMIT();
#pragma unroll
        for (int i = 0; i < 4; i++) CP_ASYNC16(saA[i] + AB_BUF * 4, gpA[i] + 32);
#pragma unroll
        for (int i = 0; i < 4; i++) CP_ASYNC16(saB[i] + AB_BUF * 4, gpB[i] + 32);
        CP_COMMIT();

#pragma unroll 1
        for (int t = 0; t < KCHUNKS; t++) {
            if (t == KCHUNKS - 1) { CP_WAIT(0); } else { CP_WAIT(1); }
            __syncthreads();
            if (t + 2 < KCHUNKS) {
                const uint32_t d = ((t + 2) % 3) * AB_BUF * 4;
#pragma unroll
                for (int i = 0; i < 4; i++) CP_ASYNC16(saA[i] + d, gpA[i] + (t + 2) * 32);
#pragma unroll
                for (int i = 0; i < 4; i++) CP_ASYNC16(saB[i] + d, gpB[i] + (t + 2) * 32);
                CP_COMMIT();
            }

            const uint32_t bufOff = (t % 3) * AB_BUF * 4;
#pragma unroll
            for (int kk = 0; kk < 32; kk += 8) {
                uint32_t a[4][4], bf[2][4];
#pragma unroll
                for (int mf = 0; mf < 4; mf++)
                    LDSM_X4(a[mf][0], a[mf][1], a[mf][2], a[mf][3],
                            sb + bufOff + aBase[mf] + kk * 4);
#pragma unroll
                for (int mf = 0; mf < 4; mf++)
#pragma unroll
                    for (int j = 0; j < 4; j++)
                        a[mf][j] = rna_bits(a[mf][j]);
#pragma unroll
                for (int p = 0; p < 2; p++)
                    LDSM_X4(bf[p][0], bf[p][1], bf[p][2], bf[p][3],
                            sb + bufOff + bBase[p] + kk * 4);
#pragma unroll
                for (int mf = 0; mf < 4; mf++)
#pragma unroll
                    for (int nf = 0; nf < 4; nf++)
                        mma_tf32(acc[mf][nf][0], acc[mf][nf][1], acc[mf][nf][2], acc[mf][nf][3],
                                 a[mf][0], a[mf][1], a[mf][2], a[mf][3],
                                 bf[nf >> 1][(nf & 1) * 2], bf[nf >> 1][(nf & 1) * 2 + 1]);
            }
        }

        if (z == 2) {
            // transposed epilogue: acc -> smem [n][m] -> g_vt coalesced
            __syncthreads();
#pragma unroll
            for (int mf = 0; mf < 4; mf++) {
#pragma unroll
                for (int nf = 0; nf < 4; nf++) {
                    int ml = wm * 64 + mf * 16 + ar;
                    int nl = wn * 32 + nf * 8 + ac * 2;
                    sm[nl * VT_PITCH + ml]           = f_rna_tf32(acc[mf][nf][0]);
                    sm[(nl + 1) * VT_PITCH + ml]     = f_rna_tf32(acc[mf][nf][1]);
                    sm[nl * VT_PITCH + ml + 8]       = f_rna_tf32(acc[mf][nf][2]);
                    sm[(nl + 1) * VT_PITCH + ml + 8] = f_rna_tf32(acc[mf][nf][3]);
                }
            }
            __syncthreads();
            const int bb = m0 >> 10;
            const int s0base = m0 & (SEQ - 1);
#pragma unroll
            for (int i = 0; i < 16; i++) {
                int idx = tid + i * 256;
                int r = idx >> 5, c4 = (idx & 31) * 4;
                int ng = n0 + r;
                int h = ng >> 6, dd = ng & 63;
                float4 v;
                v.x = sm[r * VT_PITCH + c4];     v.y = sm[r * VT_PITCH + c4 + 1];
                v.z = sm[r * VT_PITCH + c4 + 2]; v.w = sm[r * VT_PITCH + c4 + 3];
                *(float4*)&dst[(((size_t)(bb * NH + h) * HD) + dd) * SEQ + s0base + c4] = v;
            }
        } else {
            const float qs = (z == 0) ? 0.125f : 1.0f;
#pragma unroll
            for (int mf = 0; mf < 4; mf++) {
#pragma unroll
                for (int nf = 0; nf < 4; nf++) {
                    int m = m0 + wm * 64 + mf * 16 + ar;
                    int n = n0 + wn * 32 + nf * 8 + ac * 2;
                    float2 lo = make_float2(f_rna_tf32(acc[mf][nf][0] * qs),
                                            f_rna_tf32(acc[mf][nf][1] * qs));
                    float2 hi = make_float2(f_rna_tf32(acc[mf][nf][2] * qs),
                                            f_rna_tf32(acc[mf][nf][3] * qs));
                    int h = n >> 6, dd = n & 63;
                    int bb0 = m >> 10, s0 = m & 1023;
                    int bb1 = (m + 8) >> 10, s1 = (m + 8) & 1023;
                    *(float2*)&dst[(((bb0 * NH + h) * SEQ) + s0) * HD + dd] = lo;
                    *(float2*)&dst[(((bb1 * NH + h) * SEQ) + s1) * HD + dd] = hi;
                }
            }
        }
        __syncthreads();   // protect buf0/1 from next tile's prologue
    }
}

// -------------------- output GEMM (standard, single wave) -------------------
__global__ __launch_bounds__(256, 2) void gemm_out(float* __restrict__ outp)
{
    extern __shared__ float sm[];
    const uint32_t sb = smem_u32(sm);
    const int tid = threadIdx.x, lane = tid & 31, wid = tid >> 5;
    const int wm = wid >> 2, wn = wid & 3;
    const int m0 = blockIdx.y * 128, n0 = blockIdx.x * 128;

    uint32_t saA[4], saB[4];
    const float* gpA[4]; const float* gpB[4];
#pragma unroll
    for (int i = 0; i < 4; i++) {
        int s = tid + i * 256;
        int r = s >> 3, c = s & 7;
        saA[i] = sb + (r * PITCH + c * 4) * 4;
        saB[i] = sb + (3 * AB_BUF + r * PITCH + c * 4) * 4;
        gpA[i] = g_ctx + (m0 + r) * DIM + c * 4;
        gpB[i] = g_wot + (n0 + r) * DIM + c * 4;
    }

    const uint32_t laneA = ((lane & 15) * PITCH + ((lane >> 4) << 2)) * 4;
    const uint32_t laneB = (((lane & 7) + ((lane & 16) ? 8 : 0)) * PITCH +
                            ((lane & 8) ? 4 : 0)) * 4;
    uint32_t aBase[4], bBase[2];
#pragma unroll
    for (int mf = 0; mf < 4; mf++) aBase[mf] = (wm * 64 + mf * 16) * PITCH * 4 + laneA;
#pragma unroll
    for (int p = 0; p < 2; p++)
        bBase[p] = 3 * AB_BUF * 4 + (wn * 32 + p * 16) * PITCH * 4 + laneB;

    float acc[4][4][4];
#pragma unroll
    for (int mf = 0; mf < 4; mf++)
#pragma unroll
        for (int nf = 0; nf < 4; nf++)
#pragma unroll
            for (int e = 0; e < 4; e++) acc[mf][nf][e] = 0.f;

#pragma unroll
    for (int i = 0; i < 4; i++) CP_ASYNC16(saA[i], gpA[i]);
#pragma unroll
    for (int i = 0; i < 4; i++) CP_ASYNC16(saB[i], gpB[i]);
    CP_COMMIT();
#pragma unroll
    for (int i = 0; i < 4; i++) CP_ASYNC16(saA[i] + AB_BUF * 4, gpA[i] + 32);
#pragma unroll
    for (int i = 0; i < 4; i++) CP_ASYNC16(saB[i] + AB_BUF * 4, gpB[i] + 32);
    CP_COMMIT();

#pragma unroll 1
    for (int t = 0; t < KCHUNKS; t++) {
        if (t == KCHUNKS - 1) { CP_WAIT(0); } else { CP_WAIT(1); }
        __syncthreads();
        if (t + 2 < KCHUNKS) {
            const uint32_t d = ((t + 2) % 3) * AB_BUF * 4;
#pragma unroll
            for (int i = 0; i < 4; i++) CP_ASYNC16(saA[i] + d, gpA[i] + (t + 2) * 32);
#pragma unroll
            for (int i = 0; i < 4; i++) CP_ASYNC16(saB[i] + d, gpB[i] + (t + 2) * 32);
            CP_COMMIT();
        }

        const uint32_t bufOff = (t % 3) * AB_BUF * 4;
#pragma unroll
        for (int kk = 0; kk < 32; kk += 8) {
            uint32_t a[4][4], bf[2][4];
#pragma unroll
            for (int mf = 0; mf < 4; mf++)
                LDSM_X4(a[mf][0], a[mf][1], a[mf][2], a[mf][3],
                        sb + bufOff + aBase[mf] + kk * 4);
#pragma unroll
            for (int p = 0; p < 2; p++)
                LDSM_X4(bf[p][0], bf[p][1], bf[p][2], bf[p][3],
                        sb + bufOff + bBase[p] + kk * 4);
#pragma unroll
            for (int mf = 0; mf < 4; mf++)
#pragma unroll
                for (int nf = 0; nf < 4; nf++)
                    mma_tf32(acc[mf][nf][0], acc[mf][nf][1], acc[mf][nf][2], acc[mf][nf][3],
                             a[mf][0], a[mf][1], a[mf][2], a[mf][3],
                             bf[nf >> 1][(nf & 1) * 2], bf[nf >> 1][(nf & 1) * 2 + 1]);
        }
    }

    const int ar = lane >> 2, ac = lane & 3;
#pragma unroll
    for (int mf = 0; mf < 4; mf++) {
#pragma unroll
        for (int nf = 0; nf < 4; nf++) {
            int m = m0 + wm * 64 + mf * 16 + ar;
            int n = n0 + wn * 32 + nf * 8 + ac * 2;
            *(float2*)&outp[m * DIM + n] =
                make_float2(acc[mf][nf][0], acc[mf][nf][1]);
            *(float2*)&outp[(m + 8) * DIM + n] =
                make_float2(acc[mf][nf][2], acc[mf][nf][3]);
        }
    }
}

// -------------------- tensor-core flash attention (ldmatrix + shfl P) -------
#define AP 68
#define ATTN_K0 8704
#define ATTN_V0 17408
#define ATTN_SMEM_BYTES (26112 * 4)

__global__ __launch_bounds__(256) void attn_tc(const int* __restrict__ vlens)
{
    extern __shared__ float sm[];
    const uint32_t sb = smem_u32(sm);
    const int tid = threadIdx.x, lane = tid & 31, wq = tid >> 5;
    const int qt = blockIdx.x, h = blockIdx.y;

    // heavy-first batch permutation (deterministic; all threads agree)
    int vb[4] = {vlens[0], vlens[1], vlens[2], vlens[3]};
    int b = 0;
#pragma unroll
    for (int i = 0; i < 4; i++) {
        int rank = 0;
#pragma unroll
        for (int j = 0; j < 4; j++)
            rank += (vb[j] > vb[i]) || (vb[j] == vb[i] && j < i);
        if (rank == (int)blockIdx.z) b = i;
    }
    const int vlen = vb[b];
    const int ntiles = (vlen + 63) >> 6;

    const float* qb  = g_q  + ((size_t)(b * NH + h) * SEQ + qt * 128) * HD;
    const float* kb  = g_k  + ((size_t)(b * NH + h) * SEQ) * HD;
    const float* vtb = g_vt + ((size_t)(b * NH + h) * HD) * SEQ;

#pragma unroll
    for (int i = 0; i < 8; i++) {
        int idx = tid + i * 256, r = idx >> 4, c4 = (idx & 15) * 4;
        CP_ASYNC16(sb + (r * AP + c4) * 4, qb + r * HD + c4);
    }
#pragma unroll
    for (int i = 0; i < 4; i++) {
        int idx = tid + i * 256, r = idx >> 4, c4 = (idx & 15) * 4;
        CP_ASYNC16(sb + (ATTN_K0 + r * AP + c4) * 4, kb + r * HD + c4);
        CP_ASYNC16(sb + (ATTN_V0 + r * AP + c4) * 4, vtb + r * SEQ + c4);
    }
    CP_COMMIT();

    const uint32_t laneQ = ((lane & 15) * AP + ((lane >> 4) << 2)) * 4;
    const uint32_t laneP8 = (((lane & 7) + ((lane & 16) ? 8 : 0)) * AP +
                             ((lane & 8) ? 4 : 0)) * 4;
    const uint32_t qBase = wq * 16 * AP * 4 + laneQ;
    uint32_t pPair[4];
#pragma unroll
    for (int p = 0; p < 4; p++) pPair[p] = p * 16 * AP * 4 + laneP8;

    float m_run[2] = {-1e30f, -1e30f};
    float l_run[2] = {0.f, 0.f};
    float oAcc[8][4];
#pragma unroll
    for (int nf = 0; nf < 8; nf++)
#pragma unroll
        for (int e = 0; e < 4; e++) oAcc[nf][e] = 0.f;

    const int lr = lane >> 2, lc = lane & 3;

#pragma unroll 1
    for (int kt = 0; kt < ntiles; kt++) {
        CP_WAIT(0);
        __syncthreads();
        if (kt + 1 < ntiles) {
            const int nb = (kt + 1) & 1;
#pragma unroll
            for (int i = 0; i < 4; i++) {
                int idx = tid + i * 256, r = idx >> 4, c4 = (idx & 15) * 4;
                CP_ASYNC16(sb + (ATTN_K0 + nb * 4352 + r * AP + c4) * 4,
                           kb + ((kt + 1) * 64 + r) * HD + c4);
                CP_ASYNC16(sb + (ATTN_V0 + nb * 4352 + r * AP + c4) * 4,
                           vtb + r * SEQ + (kt + 1) * 64 + c4);
            }
            CP_COMMIT();
        }

        const uint32_t kBuf = (ATTN_K0 + (kt & 1) * 4352) * 4;
        const uint32_t vBuf = (ATTN_V0 + (kt & 1) * 4352) * 4;

        // ---- S = Q K^T (Q pre-scaled by 1/8) ----
        float sAcc[8][4];
#pragma unroll
        for (int nf = 0; nf < 8; nf++)
#pragma unroll
            for (int e = 0; e < 4; e++) sAcc[nf][e] = 0.f;

#pragma unroll
        for (int kk = 0; kk < 64; kk += 8) {
            uint32_t a0, a1, a2, a3, kf[4][4];
            LDSM_X4(a0, a1, a2, a3, sb + qBase + kk * 4);
#pragma unroll
            for (int p = 0; p < 4; p++)
                LDSM_X4(kf[p][0], kf[p][1], kf[p][2], kf[p][3],
                        sb + kBuf + pPair[p] + kk * 4);
#pragma unroll
            for (int nf = 0; nf < 8; nf++)
                mma_tf32(sAcc[nf][0], sAcc[nf][1], sAcc[nf][2], sAcc[nf][3],
                         a0, a1, a2, a3,
                         kf[nf >> 1][(nf & 1) * 2], kf[nf >> 1][(nf & 1) * 2 + 1]);
        }

        // ---- mask (last tile only) ----
        if (kt == ntiles - 1 && (vlen & 63)) {
#pragma unroll
            for (int nf = 0; nf < 8; nf++) {
#pragma unroll
                for (int e = 0; e < 2; e++) {
                    int col = kt * 64 + nf * 8 + 2 * lc + e;
                    if (col >= vlen) { sAcc[nf][e] = -1e6f; sAcc[nf][2 + e] = -1e6f; }
                }
            }
        }

        // ---- fragment online softmax ----
        float rmax0 = -1e30f, rmax1 = -1e30f;
#pragma unroll
        for (int nf = 0; nf < 8; nf++) {
            rmax0 = fmaxf(rmax0, fmaxf(sAcc[nf][0], sAcc[nf][1]));
            rmax1 = fmaxf(rmax1, fmaxf(sAcc[nf][2], sAcc[nf][3]));
        }
        rmax0 = fmaxf(rmax0, __shfl_xor_sync(0xffffffffu, rmax0, 1));
        rmax0 = fmaxf(rmax0, __shfl_xor_sync(0xffffffffu, rmax0, 2));
        rmax1 = fmaxf(rmax1, __shfl_xor_sync(0xffffffffu, rmax1, 1));
        rmax1 = fmaxf(rmax1, __shfl_xor_sync(0xffffffffu, rmax1, 2));

        float nm0 = fmaxf(m_run[0], rmax0), nm1 = fmaxf(m_run[1], rmax1);
        float alpha0 = __expf(m_run[0] - nm0), alpha1 = __expf(m_run[1] - nm1);
        m_run[0] = nm0; m_run[1] = nm1;

        float ts0 = 0.f, ts1 = 0.f;
#pragma unroll
        for (int nf = 0; nf < 8; nf++) {
#pragma unroll
            for (int e = 0; e < 2; e++) {
                float p0 = f_rna_tf32(__expf(sAcc[nf][e] - nm0));
                float p1 = f_rna_tf32(__expf(sAcc[nf][2 + e] - nm1));
                ts0 += p0; ts1 += p1;
                sAcc[nf][e] = p0; sAcc[nf][2 + e] = p1;
            }
        }
        ts0 += __shfl_xor_sync(0xffffffffu, ts0, 1);
        ts0 += __shfl_xor_sync(0xffffffffu, ts0, 2);
        ts1 += __shfl_xor_sync(0xffffffffu, ts1, 1);
        ts1 += __shfl_xor_sync(0xffffffffu, ts1, 2);
        l_run[0] = l_run[0] * alpha0 + ts0;
        l_run[1] = l_run[1] * alpha1 + ts1;

#pragma unroll
        for (int nf = 0; nf < 8; nf++) {
            oAcc[nf][0] *= alpha0; oAcc[nf][1] *= alpha0;
            oAcc[nf][2] *= alpha1; oAcc[nf][3] *= alpha1;
        }

        // ---- O += P V : P acc-frag -> A-frag via quad shfl ----
        const int srcA = (lane & ~3) | (lc >> 1);
        const int srcB = srcA + 2;
        const bool oddc = lc & 1;
#pragma unroll
        for (int kc = 0; kc < 8; kc++) {
            float v0 = __shfl_sync(0xffffffffu, sAcc[kc][0], srcA);
            float v1 = __shfl_sync(0xffffffffu, sAcc[kc][1], srcA);
            float v2 = __shfl_sync(0xffffffffu, sAcc[kc][2], srcA);
            float v3 = __shfl_sync(0xffffffffu, sAcc[kc][3], srcA);
            float u0 = __shfl_sync(0xffffffffu, sAcc[kc][0], srcB);
            float u1 = __shfl_sync(0xffffffffu, sAcc[kc][1], srcB);
            float u2 = __shfl_sync(0xffffffffu, sAcc[kc][2], srcB);
            float u3 = __shfl_sync(0xffffffffu, sAcc[kc][3], srcB);
            uint32_t a0 = __float_as_uint(oddc ? v1 : v0);
            uint32_t a1 = __float_as_uint(oddc ? v3 : v2);
            uint32_t a2 = __float_as_uint(oddc ? u1 : u0);
            uint32_t a3 = __float_as_uint(oddc ? u3 : u2);
            uint32_t vf[4][4];
#pragma unroll
            for (int p = 0; p < 4; p++)
                LDSM_X4(vf[p][0], vf[p][1], vf[p][2], vf[p][3],
                        sb + vBuf + pPair[p] + kc * 32);
#pragma unroll
            for (int nf = 0; nf < 8; nf++)
                mma_tf32(oAcc[nf][0], oAcc[nf][1], oAcc[nf][2], oAcc[nf][3],
                         a0, a1, a2, a3,
                         vf[nf >> 1][(nf & 1) * 2], vf[nf >> 1][(nf & 1) * 2 + 1]);
        }
    }

    // ---- epilogue ----
    float inv0 = 1.f / l_run[0], inv1 = 1.f / l_run[1];
    int row0 = qt * 128 + wq * 16 + lr;
    int row1 = row0 + 8;
#pragma unroll
    for (int nf = 0; nf < 8; nf++) {
        int col = h * HD + nf * 8 + 2 * lc;
        float2 lo = make_float2(f_rna_tf32(oAcc[nf][0] * inv0), f_rna_tf32(oAcc[nf][1] * inv0));
        float2 hi = make_float2(f_rna_tf32(oAcc[nf][2] * inv1), f_rna_tf32(oAcc[nf][3] * inv1));
        *(float2*)&g_ctx[(b * SEQ + row0) * DIM + col] = lo;
        *(float2*)&g_ctx[(b * SEQ + row1) * DIM + col] = hi;
    }
}

// ---------------------------------------------------------------------------
extern "C" void kernel_launch(void* const* d_in, const int* in_sizes, int n_in,
                              void* d_out, int out_size)
{
    const float* queries = (const float*)d_in[0];
    const float* keys    = (const float*)d_in[1];
    const float* values  = (const float*)d_in[2];
    const int*   vlens   = (const int*)d_in[3];
    const float* W_q     = (const float*)d_in[4];
    const float* W_o     = (const float*)d_in[5];
    float* out = (float*)d_out;

    cudaFuncSetAttribute(gemm_proj_persist, cudaFuncAttributeMaxDynamicSharedMemorySize, GEMM_SMEM_BYTES);
    cudaFuncSetAttribute(gemm_out, cudaFuncAttributeMaxDynamicSharedMemorySize, GEMM_SMEM_BYTES);
    cudaFuncSetAttribute(attn_tc, cudaFuncAttributeMaxDynamicSharedMemorySize, ATTN_SMEM_BYTES);

    prep_wt<<<dim3(32, 32, 2), 256>>>(W_q, W_o);
    gemm_proj_persist<<<NPERSIST, 256, GEMM_SMEM_BYTES>>>(queries, keys, values, vlens);
    attn_tc<<<dim3(SEQ / 128, NH, BATCH), 256, ATTN_SMEM_BYTES>>>(vlens);
    gemm_out<<<dim3(8, 32), 256, GEMM_SMEM_BYTES>>>(out);
}

// round 15
// speedup vs baseline: 1.1483x; 1.1483x over previous
#include <cuda_runtime.h>
#include <cstdint>

#define BATCH 4
#define SEQ   1024
#define DIM   1024
#define NH    16
#define HD    64

// -------------------- device scratch (allocation-free) ----------------------
__device__ float g_q[BATCH * NH * SEQ * HD];     // head-split, tf32-rounded, pre-scaled 1/8
__device__ float g_k[BATCH * NH * SEQ * HD];
__device__ float g_vt[BATCH * NH * HD * SEQ];    // V proj, transposed [b,h,d,s]
__device__ float g_ctx[BATCH * SEQ * DIM];       // attn output (tf32-rna rounded)
__device__ float g_wqt[DIM * DIM];               // W_q^T rounded, [n][k]
__device__ float g_wot[DIM * DIM];               // W_o^T rounded, [n][k]

// -------------------- helpers ----------------------------------------------
__device__ __forceinline__ uint32_t smem_u32(const void* p) {
    uint32_t a;
    asm("{ .reg .u64 t; cvta.to.shared.u64 t, %1; cvt.u32.u64 %0, t; }" : "=r"(a) : "l"(p));
    return a;
}
__device__ __forceinline__ float f_rna_tf32(float f) {
    uint32_t r; asm("cvt.rna.tf32.f32 %0, %1;" : "=r"(r) : "f"(f));
    return __uint_as_float(r);
}
__device__ __forceinline__ uint32_t rna_bits(uint32_t x) {
    uint32_t r; asm("cvt.rna.tf32.f32 %0, %1;" : "=r"(r) : "f"(__uint_as_float(x)));
    return r;
}

#define CP_ASYNC16(sa, gp) \
    asm volatile("cp.async.cg.shared.global [%0], [%1], 16;" :: "r"(sa), "l"(gp))
#define CP_COMMIT() asm volatile("cp.async.commit_group;" ::: "memory")
#define CP_WAIT(n)  asm volatile("cp.async.wait_group %0;" :: "n"(n) : "memory")

#define LDSM_X4(r0, r1, r2, r3, a) \
    asm volatile("ldmatrix.sync.aligned.m8n8.x4.shared.b16 {%0,%1,%2,%3}, [%4];" \
                 : "=r"(r0), "=r"(r1), "=r"(r2), "=r"(r3) : "r"(a))

__device__ __forceinline__ void mma_tf32(float& d0, float& d1, float& d2, float& d3,
                                         uint32_t a0, uint32_t a1, uint32_t a2, uint32_t a3,
                                         uint32_t b0, uint32_t b1) {
    asm volatile(
        "mma.sync.aligned.m16n8k8.row.col.f32.tf32.tf32.f32 "
        "{%0,%1,%2,%3}, {%4,%5,%6,%7}, {%8,%9}, {%0,%1,%2,%3};"
        : "+f"(d0), "+f"(d1), "+f"(d2), "+f"(d3)
        : "r"(a0), "r"(a1), "r"(a2), "r"(a3), "r"(b0), "r"(b1));
}

// -------------------- prep: transpose + round weights -----------------------
__global__ void prep_wt(const float* __restrict__ Wq, const float* __restrict__ Wo)
{
    const float* src = blockIdx.z ? Wo : Wq;
    float* dst = blockIdx.z ? g_wot : g_wqt;
    __shared__ float t[32][33];
    const int tid = threadIdx.x;
    const int n0 = blockIdx.x * 32, k0 = blockIdx.y * 32;
#pragma unroll
    for (int i = 0; i < 4; i++) {
        int idx = tid + i * 256, r = idx >> 5, c = idx & 31;
        t[r][c] = src[(k0 + r) * DIM + n0 + c];
    }
    __syncthreads();
#pragma unroll
    for (int i = 0; i < 4; i++) {
        int idx = tid + i * 256, r = idx >> 5, c = idx & 31;
        dst[(n0 + r) * DIM + k0 + c] = f_rna_tf32(t[c][r]);
    }
}

// -------------------- tf32 mma.sync GEMM, ldmatrix operand loads ------------
#define PITCH 36
#define AB_BUF (128 * PITCH)
#define GEMM_SMEM_BYTES (6 * AB_BUF * 4)     // 110592
#define KCHUNKS 32
#define VT_PITCH 132

// MODE 0: proj from RAW inputs (A rounded in-loop after ldmatrix).
//   z=0: queries (pre-scaled 1/8 in epilogue) -> g_q
//   z=1: keys -> g_k      z=2: values -> g_vt (directly transposed)
// MODE 1: out  (g_ctx [pre-rounded] @ g_wot -> outp plain; no in-loop cvt)
template<int MODE>
__global__ __launch_bounds__(256, 2) void gemm_mma(
    const float* __restrict__ A0, const float* __restrict__ A1,
    const float* __restrict__ A2, float* __restrict__ outp,
    const int* __restrict__ vlens)
{
    extern __shared__ float sm[];
    const uint32_t sb = smem_u32(sm);
    const int tid = threadIdx.x, lane = tid & 31, wid = tid >> 5;
    const int wm = wid >> 2, wn = wid & 3;           // warp grid 2x4
    const int m0 = blockIdx.y * 128, n0 = blockIdx.x * 128;
    const int z = (MODE == 0) ? blockIdx.z : 0;

    const float* A; const float* B; float* dst;
    if (MODE == 0) {
        A   = (z == 0) ? A0  : (z == 1) ? A1  : A2;
        dst = (z == 0) ? g_q : (z == 1) ? g_k : g_vt;
        B   = g_wqt;
        if (z != 0 && (m0 & (SEQ - 1)) >= vlens[m0 >> 10]) return;
    } else {
        A = g_ctx; dst = outp; B = g_wot;
    }

    uint32_t saA[4], saB[4];
    const float* gpA[4]; const float* gpB[4];
#pragma unroll
    for (int i = 0; i < 4; i++) {
        int s = tid + i * 256;
        int r = s >> 3, c = s & 7;
        saA[i] = sb + (r * PITCH + c * 4) * 4;
        saB[i] = sb + (3 * AB_BUF + r * PITCH + c * 4) * 4;
        gpA[i] = A + (m0 + r) * DIM + c * 4;
        gpB[i] = B + (n0 + r) * DIM + c * 4;
    }

    const uint32_t laneA = ((lane & 15) * PITCH + ((lane >> 4) << 2)) * 4;
    const uint32_t laneB = (((lane & 7) + ((lane & 16) ? 8 : 0)) * PITCH +
                            ((lane & 8) ? 4 : 0)) * 4;
    uint32_t aBase[4], bBase[2];
#pragma unroll
    for (int mf = 0; mf < 4; mf++) aBase[mf] = (wm * 64 + mf * 16) * PITCH * 4 + laneA;
#pragma unroll
    for (int p = 0; p < 2; p++)
        bBase[p] = 3 * AB_BUF * 4 + (wn * 32 + p * 16) * PITCH * 4 + laneB;

    float acc[4][4][4];
#pragma unroll
    for (int mf = 0; mf < 4; mf++)
#pragma unroll
        for (int nf = 0; nf < 4; nf++)
#pragma unroll
            for (int e = 0; e < 4; e++) acc[mf][nf][e] = 0.f;

#pragma unroll
    for (int i = 0; i < 4; i++) CP_ASYNC16(saA[i], gpA[i]);
#pragma unroll
    for (int i = 0; i < 4; i++) CP_ASYNC16(saB[i], gpB[i]);
    CP_COMMIT();
#pragma unroll
    for (int i = 0; i < 4; i++) CP_ASYNC16(saA[i] + AB_BUF * 4, gpA[i] + 32);
#pragma unroll
    for (int i = 0; i < 4; i++) CP_ASYNC16(saB[i] + AB_BUF * 4, gpB[i] + 32);
    CP_COMMIT();

#pragma unroll 1
    for (int t = 0; t < KCHUNKS; t++) {
        if (t == KCHUNKS - 1) { CP_WAIT(0); } else { CP_WAIT(1); }
        __syncthreads();
        if (t + 2 < KCHUNKS) {
            const uint32_t d = ((t + 2) % 3) * AB_BUF * 4;
#pragma unroll
            for (int i = 0; i < 4; i++) CP_ASYNC16(saA[i] + d, gpA[i] + (t + 2) * 32);
#pragma unroll
            for (int i = 0; i < 4; i++) CP_ASYNC16(saB[i] + d, gpB[i] + (t + 2) * 32);
            CP_COMMIT();
        }

        const uint32_t bufOff = (t % 3) * AB_BUF * 4;
#pragma unroll
        for (int kk = 0; kk < 32; kk += 8) {
            uint32_t a[4][4], bf[2][4];
#pragma unroll
            for (int mf = 0; mf < 4; mf++)
                LDSM_X4(a[mf][0], a[mf][1], a[mf][2], a[mf][3],
                        sb + bufOff + aBase[mf] + kk * 4);
            if (MODE == 0) {
#pragma unroll
                for (int mf = 0; mf < 4; mf++)
#pragma unroll
                    for (int j = 0; j < 4; j++)
                        a[mf][j] = rna_bits(a[mf][j]);
            }
#pragma unroll
            for (int p = 0; p < 2; p++)
                LDSM_X4(bf[p][0], bf[p][1], bf[p][2], bf[p][3],
                        sb + bufOff + bBase[p] + kk * 4);
#pragma unroll
            for (int mf = 0; mf < 4; mf++)
#pragma unroll
                for (int nf = 0; nf < 4; nf++)
                    mma_tf32(acc[mf][nf][0], acc[mf][nf][1], acc[mf][nf][2], acc[mf][nf][3],
                             a[mf][0], a[mf][1], a[mf][2], a[mf][3],
                             bf[nf >> 1][(nf & 1) * 2], bf[nf >> 1][(nf & 1) * 2 + 1]);
        }
    }

    const int ar = lane >> 2, ac = lane & 3;

    if (MODE == 0 && z == 2) {
        // ---- transposed epilogue: acc -> smem [n][m] -> g_vt coalesced ----
        __syncthreads();   // operand buffers dead; reuse as scratch
#pragma unroll
        for (int mf = 0; mf < 4; mf++) {
#pragma unroll
            for (int nf = 0; nf < 4; nf++) {
                int ml = wm * 64 + mf * 16 + ar;
                int nl = wn * 32 + nf * 8 + ac * 2;
                sm[nl * VT_PITCH + ml]           = f_rna_tf32(acc[mf][nf][0]);
                sm[(nl + 1) * VT_PITCH + ml]     = f_rna_tf32(acc[mf][nf][1]);
                sm[nl * VT_PITCH + ml + 8]       = f_rna_tf32(acc[mf][nf][2]);
                sm[(nl + 1) * VT_PITCH + ml + 8] = f_rna_tf32(acc[mf][nf][3]);
            }
        }
        __syncthreads();
        const int bb = m0 >> 10;
        const int s0base = m0 & (SEQ - 1);     // batch-local s offset
#pragma unroll
        for (int i = 0; i < 16; i++) {
            int idx = tid + i * 256;
            int r = idx >> 5, c4 = (idx & 31) * 4;
            int ng = n0 + r;
            int h = ng >> 6, dd = ng & 63;
            float4 v;
            v.x = sm[r * VT_PITCH + c4];     v.y = sm[r * VT_PITCH + c4 + 1];
            v.z = sm[r * VT_PITCH + c4 + 2]; v.w = sm[r * VT_PITCH + c4 + 3];
            *(float4*)&dst[(((size_t)(bb * NH + h) * HD) + dd) * SEQ + s0base + c4] = v;
        }
        return;
    }

    const float qs = (MODE == 0 && z == 0) ? 0.125f : 1.0f;
#pragma unroll
    for (int mf = 0; mf < 4; mf++) {
#pragma unroll
        for (int nf = 0; nf < 4; nf++) {
            int m = m0 + wm * 64 + mf * 16 + ar;
            int n = n0 + wn * 32 + nf * 8 + ac * 2;
            if (MODE == 0) {
                float2 lo = make_float2(f_rna_tf32(acc[mf][nf][0] * qs),
                                        f_rna_tf32(acc[mf][nf][1] * qs));
                float2 hi = make_float2(f_rna_tf32(acc[mf][nf][2] * qs),
                                        f_rna_tf32(acc[mf][nf][3] * qs));
                int h = n >> 6, dd = n & 63;
                int bb0 = m >> 10, s0 = m & 1023;
                int bb1 = (m + 8) >> 10, s1 = (m + 8) & 1023;
                *(float2*)&dst[(((bb0 * NH + h) * SEQ) + s0) * HD + dd] = lo;
                *(float2*)&dst[(((bb1 * NH + h) * SEQ) + s1) * HD + dd] = hi;
            } else {
                *(float2*)&dst[m * DIM + n] =
                    make_float2(acc[mf][nf][0], acc[mf][nf][1]);
                *(float2*)&dst[(m + 8) * DIM + n] =
                    make_float2(acc[mf][nf][2], acc[mf][nf][3]);
            }
        }
    }
}

// -------------------- tensor-core flash attention (ldmatrix + shfl P) -------
// 128 q-rows, 8 warps, 104448 B smem => 2 CTA/SM. Heavy-batch-first via
// per-block permutation of blockIdx.z (sorted by descending vlen).
#define AP 68
#define ATTN_K0 8704
#define ATTN_V0 17408
#define ATTN_SMEM_BYTES (26112 * 4)

__global__ __launch_bounds__(256) void attn_tc(const int* __restrict__ vlens)
{
    extern __shared__ float sm[];
    const uint32_t sb = smem_u32(sm);
    const int tid = threadIdx.x, lane = tid & 31, wq = tid >> 5;
    const int qt = blockIdx.x, h = blockIdx.y;

    // heavy-first batch permutation (deterministic; all threads agree)
    int vb[4] = {vlens[0], vlens[1], vlens[2], vlens[3]};
    int b = 0;
#pragma unroll
    for (int i = 0; i < 4; i++) {
        int rank = 0;
#pragma unroll
        for (int j = 0; j < 4; j++)
            rank += (vb[j] > vb[i]) || (vb[j] == vb[i] && j < i);
        if (rank == (int)blockIdx.z) b = i;
    }
    const int vlen = vb[b];
    const int ntiles = (vlen + 63) >> 6;

    const float* qb  = g_q  + ((size_t)(b * NH + h) * SEQ + qt * 128) * HD;
    const float* kb  = g_k  + ((size_t)(b * NH + h) * SEQ) * HD;
    const float* vtb = g_vt + ((size_t)(b * NH + h) * HD) * SEQ;

#pragma unroll
    for (int i = 0; i < 8; i++) {
        int idx = tid + i * 256, r = idx >> 4, c4 = (idx & 15) * 4;
        CP_ASYNC16(sb + (r * AP + c4) * 4, qb + r * HD + c4);
    }
#pragma unroll
    for (int i = 0; i < 4; i++) {
        int idx = tid + i * 256, r = idx >> 4, c4 = (idx & 15) * 4;
        CP_ASYNC16(sb + (ATTN_K0 + r * AP + c4) * 4, kb + r * HD + c4);
        CP_ASYNC16(sb + (ATTN_V0 + r * AP + c4) * 4, vtb + r * SEQ + c4);
    }
    CP_COMMIT();

    const uint32_t laneQ = ((lane & 15) * AP + ((lane >> 4) << 2)) * 4;
    const uint32_t laneP8 = (((lane & 7) + ((lane & 16) ? 8 : 0)) * AP +
                             ((lane & 8) ? 4 : 0)) * 4;
    const uint32_t qBase = wq * 16 * AP * 4 + laneQ;
    uint32_t pPair[4];
#pragma unroll
    for (int p = 0; p < 4; p++) pPair[p] = p * 16 * AP * 4 + laneP8;

    float m_run[2] = {-1e30f, -1e30f};
    float l_run[2] = {0.f, 0.f};
    float oAcc[8][4];
#pragma unroll
    for (int nf = 0; nf < 8; nf++)
#pragma unroll
        for (int e = 0; e < 4; e++) oAcc[nf][e] = 0.f;

    const int lr = lane >> 2, lc = lane & 3;

#pragma unroll 1
    for (int kt = 0; kt < ntiles; kt++) {
        CP_WAIT(0);
        __syncthreads();
        if (kt + 1 < ntiles) {
            const int nb = (kt + 1) & 1;
#pragma unroll
            for (int i = 0; i < 4; i++) {
                int idx = tid + i * 256, r = idx >> 4, c4 = (idx & 15) * 4;
                CP_ASYNC16(sb + (ATTN_K0 + nb * 4352 + r * AP + c4) * 4,
                           kb + ((kt + 1) * 64 + r) * HD + c4);
                CP_ASYNC16(sb + (ATTN_V0 + nb * 4352 + r * AP + c4) * 4,
                           vtb + r * SEQ + (kt + 1) * 64 + c4);
            }
            CP_COMMIT();
        }

        const uint32_t kBuf = (ATTN_K0 + (kt & 1) * 4352) * 4;
        const uint32_t vBuf = (ATTN_V0 + (kt & 1) * 4352) * 4;

        // ---- S = Q K^T (Q pre-scaled by 1/8) ----
        float sAcc[8][4];
#pragma unroll
        for (int nf = 0; nf < 8; nf++)
#pragma unroll
            for (int e = 0; e < 4; e++) sAcc[nf][e] = 0.f;

#pragma unroll
        for (int kk = 0; kk < 64; kk += 8) {
            uint32_t a0, a1, a2, a3, kf[4][4];
            LDSM_X4(a0, a1, a2, a3, sb + qBase + kk * 4);
#pragma unroll
            for (int p = 0; p < 4; p++)
                LDSM_X4(kf[p][0], kf[p][1], kf[p][2], kf[p][3],
                        sb + kBuf + pPair[p] + kk * 4);
#pragma unroll
            for (int nf = 0; nf < 8; nf++)
                mma_tf32(sAcc[nf][0], sAcc[nf][1], sAcc[nf][2], sAcc[nf][3],
                         a0, a1, a2, a3,
                         kf[nf >> 1][(nf & 1) * 2], kf[nf >> 1][(nf & 1) * 2 + 1]);
        }

        // ---- mask (last tile only) ----
        if (kt == ntiles - 1 && (vlen & 63)) {
#pragma unroll
            for (int nf = 0; nf < 8; nf++) {
#pragma unroll
                for (int e = 0; e < 2; e++) {
                    int col = kt * 64 + nf * 8 + 2 * lc + e;
                    if (col >= vlen) { sAcc[nf][e] = -1e6f; sAcc[nf][2 + e] = -1e6f; }
                }
            }
        }

        // ---- fragment online softmax ----
        float rmax0 = -1e30f, rmax1 = -1e30f;
#pragma unroll
        for (int nf = 0; nf < 8; nf++) {
            rmax0 = fmaxf(rmax0, fmaxf(sAcc[nf][0], sAcc[nf][1]));
            rmax1 = fmaxf(rmax1, fmaxf(sAcc[nf][2], sAcc[nf][3]));
        }
        rmax0 = fmaxf(rmax0, __shfl_xor_sync(0xffffffffu, rmax0, 1));
        rmax0 = fmaxf(rmax0, __shfl_xor_sync(0xffffffffu, rmax0, 2));
        rmax1 = fmaxf(rmax1, __shfl_xor_sync(0xffffffffu, rmax1, 1));
        rmax1 = fmaxf(rmax1, __shfl_xor_sync(0xffffffffu, rmax1, 2));

        float nm0 = fmaxf(m_run[0], rmax0), nm1 = fmaxf(m_run[1], rmax1);
        float alpha0 = __expf(m_run[0] - nm0), alpha1 = __expf(m_run[1] - nm1);
        m_run[0] = nm0; m_run[1] = nm1;

        float ts0 = 0.f, ts1 = 0.f;
#pragma unroll
        for (int nf = 0; nf < 8; nf++) {
#pragma unroll
            for (int e = 0; e < 2; e++) {
                float p0 = f_rna_tf32(__expf(sAcc[nf][e] - nm0));
                float p1 = f_rna_tf32(__expf(sAcc[nf][2 + e] - nm1));
                ts0 += p0; ts1 += p1;
                sAcc[nf][e] = p0; sAcc[nf][2 + e] = p1;
            }
        }
        ts0 += __shfl_xor_sync(0xffffffffu, ts0, 1);
        ts0 += __shfl_xor_sync(0xffffffffu, ts0, 2);
        ts1 += __shfl_xor_sync(0xffffffffu, ts1, 1);
        ts1 += __shfl_xor_sync(0xffffffffu, ts1, 2);
        l_run[0] = l_run[0] * alpha0 + ts0;
        l_run[1] = l_run[1] * alpha1 + ts1;

#pragma unroll
        for (int nf = 0; nf < 8; nf++) {
            oAcc[nf][0] *= alpha0; oAcc[nf][1] *= alpha0;
            oAcc[nf][2] *= alpha1; oAcc[nf][3] *= alpha1;
        }

        // ---- O += P V : P acc-frag -> A-frag via quad shfl ----
        const int srcA = (lane & ~3) | (lc >> 1);
        const int srcB = srcA + 2;
        const bool oddc = lc & 1;
#pragma unroll
        for (int kc = 0; kc < 8; kc++) {
            float v0 = __shfl_sync(0xffffffffu, sAcc[kc][0], srcA);
            float v1 = __shfl_sync(0xffffffffu, sAcc[kc][1], srcA);
            float v2 = __shfl_sync(0xffffffffu, sAcc[kc][2], srcA);
            float v3 = __shfl_sync(0xffffffffu, sAcc[kc][3], srcA);
            float u0 = __shfl_sync(0xffffffffu, sAcc[kc][0], srcB);
            float u1 = __shfl_sync(0xffffffffu, sAcc[kc][1], srcB);
            float u2 = __shfl_sync(0xffffffffu, sAcc[kc][2], srcB);
            float u3 = __shfl_sync(0xffffffffu, sAcc[kc][3], srcB);
            uint32_t a0 = __float_as_uint(oddc ? v1 : v0);
            uint32_t a1 = __float_as_uint(oddc ? v3 : v2);
            uint32_t a2 = __float_as_uint(oddc ? u1 : u0);
            uint32_t a3 = __float_as_uint(oddc ? u3 : u2);
            uint32_t vf[4][4];
#pragma unroll
            for (int p = 0; p < 4; p++)
                LDSM_X4(vf[p][0], vf[p][1], vf[p][2], vf[p][3],
                        sb + vBuf + pPair[p] + kc * 32);
#pragma unroll
            for (int nf = 0; nf < 8; nf++)
                mma_tf32(oAcc[nf][0], oAcc[nf][1], oAcc[nf][2], oAcc[nf][3],
                         a0, a1, a2, a3,
                         vf[nf >> 1][(nf & 1) * 2], vf[nf >> 1][(nf & 1) * 2 + 1]);
        }
    }

    // ---- epilogue ----
    float inv0 = 1.f / l_run[0], inv1 = 1.f / l_run[1];
    int row0 = qt * 128 + wq * 16 + lr;
    int row1 = row0 + 8;
#pragma unroll
    for (int nf = 0; nf < 8; nf++) {
        int col = h * HD + nf * 8 + 2 * lc;
        float2 lo = make_float2(f_rna_tf32(oAcc[nf][0] * inv0), f_rna_tf32(oAcc[nf][1] * inv0));
        float2 hi = make_float2(f_rna_tf32(oAcc[nf][2] * inv1), f_rna_tf32(oAcc[nf][3] * inv1));
        *(float2*)&g_ctx[(b * SEQ + row0) * DIM + col] = lo;
        *(float2*)&g_ctx[(b * SEQ + row1) * DIM + col] = hi;
    }
}

// ---------------------------------------------------------------------------
extern "C" void kernel_launch(void* const* d_in, const int* in_sizes, int n_in,
                              void* d_out, int out_size)
{
    const float* queries = (const float*)d_in[0];
    const float* keys    = (const float*)d_in[1];
    const float* values  = (const float*)d_in[2];
    const int*   vlens   = (const int*)d_in[3];
    const float* W_q     = (const float*)d_in[4];
    const float* W_o     = (const float*)d_in[5];
    float* out = (float*)d_out;

    cudaFuncSetAttribute(gemm_mma<0>, cudaFuncAttributeMaxDynamicSharedMemorySize, GEMM_SMEM_BYTES);
    cudaFuncSetAttribute(gemm_mma<1>, cudaFuncAttributeMaxDynamicSharedMemorySize, GEMM_SMEM_BYTES);
    cudaFuncSetAttribute(attn_tc, cudaFuncAttributeMaxDynamicSharedMemorySize, ATTN_SMEM_BYTES);

    prep_wt<<<dim3(32, 32, 2), 256>>>(W_q, W_o);
    gemm_mma<0><<<dim3(8, 32, 3), 256, GEMM_SMEM_BYTES>>>(queries, keys, values, nullptr, vlens);
    attn_tc<<<dim3(SEQ / 128, NH, BATCH), 256, ATTN_SMEM_BYTES>>>(vlens);
    gemm_mma<1><<<dim3(8, 32, 1), 256, GEMM_SMEM_BYTES>>>(nullptr, nullptr, nullptr, out, vlens);
}

// round 16
// speedup vs baseline: 1.1589x; 1.0092x over previous
#include <cuda_runtime.h>
#include <cstdint>

#define BATCH 4
#define SEQ   1024
#define DIM   1024
#define NH    16
#define HD    64

// -------------------- device scratch (allocation-free) ----------------------
__device__ float g_q[BATCH * NH * SEQ * HD];     // head-split, tf32-rounded, pre-scaled 1/8
__device__ float g_k[BATCH * NH * SEQ * HD];
__device__ float g_vt[BATCH * NH * HD * SEQ];    // V proj, transposed [b,h,d,s]
__device__ float g_ctx[BATCH * SEQ * DIM];       // attn output (tf32-rna rounded)
__device__ float g_wqt[DIM * DIM];               // W_q^T rounded, [n][k]
__device__ float g_wot[DIM * DIM];               // W_o^T rounded, [n][k]

// -------------------- helpers ----------------------------------------------
__device__ __forceinline__ uint32_t smem_u32(const void* p) {
    uint32_t a;
    asm("{ .reg .u64 t; cvta.to.shared.u64 t, %1; cvt.u32.u64 %0, t; }" : "=r"(a) : "l"(p));
    return a;
}
__device__ __forceinline__ float f_rna_tf32(float f) {
    uint32_t r; asm("cvt.rna.tf32.f32 %0, %1;" : "=r"(r) : "f"(f));
    return __uint_as_float(r);
}
__device__ __forceinline__ uint32_t rna_bits(uint32_t x) {
    uint32_t r; asm("cvt.rna.tf32.f32 %0, %1;" : "=r"(r) : "f"(__uint_as_float(x)));
    return r;
}

#define CP_ASYNC16(sa, gp) \
    asm volatile("cp.async.cg.shared.global [%0], [%1], 16;" :: "r"(sa), "l"(gp))
#define CP_COMMIT() asm volatile("cp.async.commit_group;" ::: "memory")
#define CP_WAIT(n)  asm volatile("cp.async.wait_group %0;" :: "n"(n) : "memory")

#define LDSM_X4(r0, r1, r2, r3, a) \
    asm volatile("ldmatrix.sync.aligned.m8n8.x4.shared.b16 {%0,%1,%2,%3}, [%4];" \
                 : "=r"(r0), "=r"(r1), "=r"(r2), "=r"(r3) : "r"(a))

__device__ __forceinline__ void mma_tf32(float& d0, float& d1, float& d2, float& d3,
                                         uint32_t a0, uint32_t a1, uint32_t a2, uint32_t a3,
                                         uint32_t b0, uint32_t b1) {
    asm volatile(
        "mma.sync.aligned.m16n8k8.row.col.f32.tf32.tf32.f32 "
        "{%0,%1,%2,%3}, {%4,%5,%6,%7}, {%8,%9}, {%0,%1,%2,%3};"
        : "+f"(d0), "+f"(d1), "+f"(d2), "+f"(d3)
        : "r"(a0), "r"(a1), "r"(a2), "r"(a3), "r"(b0), "r"(b1));
}

// -------------------- prep: transpose + round weights -----------------------
__global__ void prep_wt(const float* __restrict__ Wq, const float* __restrict__ Wo)
{
    const float* src = blockIdx.z ? Wo : Wq;
    float* dst = blockIdx.z ? g_wot : g_wqt;
    __shared__ float t[32][33];
    const int tid = threadIdx.x;
    const int n0 = blockIdx.x * 32, k0 = blockIdx.y * 32;
#pragma unroll
    for (int i = 0; i < 4; i++) {
        int idx = tid + i * 256, r = idx >> 5, c = idx & 31;
        t[r][c] = src[(k0 + r) * DIM + n0 + c];
    }
    __syncthreads();
#pragma unroll
    for (int i = 0; i < 4; i++) {
        int idx = tid + i * 256, r = idx >> 5, c = idx & 31;
        dst[(n0 + r) * DIM + k0 + c] = f_rna_tf32(t[c][r]);
    }
}

// -------------------- tf32 mma.sync GEMM, ldmatrix operand loads ------------
#define PITCH 36
#define AB_BUF (128 * PITCH)
#define GEMM_SMEM_BYTES (6 * AB_BUF * 4)     // 110592
#define KCHUNKS 32
#define VT_PITCH 132

// MODE 0: proj from RAW inputs (A rounded in-loop after ldmatrix).
//   z=0: queries (pre-scaled 1/8 in epilogue) -> g_q
//   z=1: keys -> g_k      z=2: values -> g_vt (directly transposed)
// MODE 1: out  (g_ctx [pre-rounded] @ g_wot -> outp plain; no in-loop cvt)
template<int MODE>
__global__ __launch_bounds__(256, 2) void gemm_mma(
    const float* __restrict__ A0, const float* __restrict__ A1,
    const float* __restrict__ A2, float* __restrict__ outp,
    const int* __restrict__ vlens)
{
    extern __shared__ float sm[];
    const uint32_t sb = smem_u32(sm);
    const int tid = threadIdx.x, lane = tid & 31, wid = tid >> 5;
    const int wm = wid >> 2, wn = wid & 3;           // warp grid 2x4
    const int m0 = blockIdx.y * 128, n0 = blockIdx.x * 128;
    const int z = (MODE == 0) ? blockIdx.z : 0;

    const float* A; const float* B; float* dst;
    if (MODE == 0) {
        A   = (z == 0) ? A0  : (z == 1) ? A1  : A2;
        dst = (z == 0) ? g_q : (z == 1) ? g_k : g_vt;
        B   = g_wqt;
        if (z != 0 && (m0 & (SEQ - 1)) >= vlens[m0 >> 10]) return;
    } else {
        A = g_ctx; dst = outp; B = g_wot;
    }

    uint32_t saA[4], saB[4];
    const float* gpA[4]; const float* gpB[4];
#pragma unroll
    for (int i = 0; i < 4; i++) {
        int s = tid + i * 256;
        int r = s >> 3, c = s & 7;
        saA[i] = sb + (r * PITCH + c * 4) * 4;
        saB[i] = sb + (3 * AB_BUF + r * PITCH + c * 4) * 4;
        gpA[i] = A + (m0 + r) * DIM + c * 4;
        gpB[i] = B + (n0 + r) * DIM + c * 4;
    }

    const uint32_t laneA = ((lane & 15) * PITCH + ((lane >> 4) << 2)) * 4;
    const uint32_t laneB = (((lane & 7) + ((lane & 16) ? 8 : 0)) * PITCH +
                            ((lane & 8) ? 4 : 0)) * 4;
    uint32_t aBase[4], bBase[2];
#pragma unroll
    for (int mf = 0; mf < 4; mf++) aBase[mf] = (wm * 64 + mf * 16) * PITCH * 4 + laneA;
#pragma unroll
    for (int p = 0; p < 2; p++)
        bBase[p] = 3 * AB_BUF * 4 + (wn * 32 + p * 16) * PITCH * 4 + laneB;

    float acc[4][4][4];
#pragma unroll
    for (int mf = 0; mf < 4; mf++)
#pragma unroll
        for (int nf = 0; nf < 4; nf++)
#pragma unroll
            for (int e = 0; e < 4; e++) acc[mf][nf][e] = 0.f;

#pragma unroll
    for (int i = 0; i < 4; i++) CP_ASYNC16(saA[i], gpA[i]);
#pragma unroll
    for (int i = 0; i < 4; i++) CP_ASYNC16(saB[i], gpB[i]);
    CP_COMMIT();
#pragma unroll
    for (int i = 0; i < 4; i++) CP_ASYNC16(saA[i] + AB_BUF * 4, gpA[i] + 32);
#pragma unroll
    for (int i = 0; i < 4; i++) CP_ASYNC16(saB[i] + AB_BUF * 4, gpB[i] + 32);
    CP_COMMIT();

#pragma unroll 1
    for (int t = 0; t < KCHUNKS; t++) {
        if (t == KCHUNKS - 1) { CP_WAIT(0); } else { CP_WAIT(1); }
        __syncthreads();
        if (t + 2 < KCHUNKS) {
            const uint32_t d = ((t + 2) % 3) * AB_BUF * 4;
#pragma unroll
            for (int i = 0; i < 4; i++) CP_ASYNC16(saA[i] + d, gpA[i] + (t + 2) * 32);
#pragma unroll
            for (int i = 0; i < 4; i++) CP_ASYNC16(saB[i] + d, gpB[i] + (t + 2) * 32);
            CP_COMMIT();
        }

        const uint32_t bufOff = (t % 3) * AB_BUF * 4;
#pragma unroll
        for (int kk = 0; kk < 32; kk += 8) {
            uint32_t a[4][4], bf[2][4];
#pragma unroll
            for (int mf = 0; mf < 4; mf++)
                LDSM_X4(a[mf][0], a[mf][1], a[mf][2], a[mf][3],
                        sb + bufOff + aBase[mf] + kk * 4);
            if (MODE == 0) {
#pragma unroll
                for (int mf = 0; mf < 4; mf++)
#pragma unroll
                    for (int j = 0; j < 4; j++)
                        a[mf][j] = rna_bits(a[mf][j]);
            }
#pragma unroll
            for (int p = 0; p < 2; p++)
                LDSM_X4(bf[p][0], bf[p][1], bf[p][2], bf[p][3],
                        sb + bufOff + bBase[p] + kk * 4);
#pragma unroll
            for (int mf = 0; mf < 4; mf++)
#pragma unroll
                for (int nf = 0; nf < 4; nf++)
                    mma_tf32(acc[mf][nf][0], acc[mf][nf][1], acc[mf][nf][2], acc[mf][nf][3],
                             a[mf][0], a[mf][1], a[mf][2], a[mf][3],
                             bf[nf >> 1][(nf & 1) * 2], bf[nf >> 1][(nf & 1) * 2 + 1]);
        }
    }

    const int ar = lane >> 2, ac = lane & 3;

    if (MODE == 0 && z == 2) {
        // ---- transposed epilogue: acc -> smem [n][m] -> g_vt coalesced ----
        __syncthreads();   // operand buffers dead; reuse as scratch
#pragma unroll
        for (int mf = 0; mf < 4; mf++) {
#pragma unroll
            for (int nf = 0; nf < 4; nf++) {
                int ml = wm * 64 + mf * 16 + ar;
                int nl = wn * 32 + nf * 8 + ac * 2;
                sm[nl * VT_PITCH + ml]           = f_rna_tf32(acc[mf][nf][0]);
                sm[(nl + 1) * VT_PITCH + ml]     = f_rna_tf32(acc[mf][nf][1]);
                sm[nl * VT_PITCH + ml + 8]       = f_rna_tf32(acc[mf][nf][2]);
                sm[(nl + 1) * VT_PITCH + ml + 8] = f_rna_tf32(acc[mf][nf][3]);
            }
        }
        __syncthreads();
        const int bb = m0 >> 10;
        const int s0base = m0 & (SEQ - 1);     // batch-local s offset
#pragma unroll
        for (int i = 0; i < 16; i++) {
            int idx = tid + i * 256;
            int r = idx >> 5, c4 = (idx & 31) * 4;
            int ng = n0 + r;
            int h = ng >> 6, dd = ng & 63;
            float4 v;
            v.x = sm[r * VT_PITCH + c4];     v.y = sm[r * VT_PITCH + c4 + 1];
            v.z = sm[r * VT_PITCH + c4 + 2]; v.w = sm[r * VT_PITCH + c4 + 3];
            *(float4*)&dst[(((size_t)(bb * NH + h) * HD) + dd) * SEQ + s0base + c4] = v;
        }
        return;
    }

    const float qs = (MODE == 0 && z == 0) ? 0.125f : 1.0f;
#pragma unroll
    for (int mf = 0; mf < 4; mf++) {
#pragma unroll
        for (int nf = 0; nf < 4; nf++) {
            int m = m0 + wm * 64 + mf * 16 + ar;
            int n = n0 + wn * 32 + nf * 8 + ac * 2;
            if (MODE == 0) {
                float2 lo = make_float2(f_rna_tf32(acc[mf][nf][0] * qs),
                                        f_rna_tf32(acc[mf][nf][1] * qs));
                float2 hi = make_float2(f_rna_tf32(acc[mf][nf][2] * qs),
                                        f_rna_tf32(acc[mf][nf][3] * qs));
                int h = n >> 6, dd = n & 63;
                int bb0 = m >> 10, s0 = m & 1023;
                int bb1 = (m + 8) >> 10, s1 = (m + 8) & 1023;
                *(float2*)&dst[(((bb0 * NH + h) * SEQ) + s0) * HD + dd] = lo;
                *(float2*)&dst[(((bb1 * NH + h) * SEQ) + s1) * HD + dd] = hi;
            } else {
                *(float2*)&dst[m * DIM + n] =
                    make_float2(acc[mf][nf][0], acc[mf][nf][1]);
                *(float2*)&dst[(m + 8) * DIM + n] =
                    make_float2(acc[mf][nf][2], acc[mf][nf][3]);
            }
        }
    }
}

// -------------------- tensor-core flash attention (ldmatrix + shfl P) -------
// 128 q-rows, 8 warps, 104448 B smem => 2 CTA/SM. Heavy-batch-first via
// per-block permutation of blockIdx.z (sorted by descending vlen).
// P fed to the PV MMA as raw fp32 (implicit tf32 truncation by HMMA).
#define AP 68
#define ATTN_K0 8704
#define ATTN_V0 17408
#define ATTN_SMEM_BYTES (26112 * 4)

__global__ __launch_bounds__(256) void attn_tc(const int* __restrict__ vlens)
{
    extern __shared__ float sm[];
    const uint32_t sb = smem_u32(sm);
    const int tid = threadIdx.x, lane = tid & 31, wq = tid >> 5;
    const int qt = blockIdx.x, h = blockIdx.y;

    // heavy-first batch permutation (deterministic; all threads agree)
    int vb[4] = {vlens[0], vlens[1], vlens[2], vlens[3]};
    int b = 0;
#pragma unroll
    for (int i = 0; i < 4; i++) {
        int rank = 0;
#pragma unroll
        for (int j = 0; j < 4; j++)
            rank += (vb[j] > vb[i]) || (vb[j] == vb[i] && j < i);
        if (rank == (int)blockIdx.z) b = i;
    }
    const int vlen = vb[b];
    const int ntiles = (vlen + 63) >> 6;

    const float* qb  = g_q  + ((size_t)(b * NH + h) * SEQ + qt * 128) * HD;
    const float* kb  = g_k  + ((size_t)(b * NH + h) * SEQ) * HD;
    const float* vtb = g_vt + ((size_t)(b * NH + h) * HD) * SEQ;

#pragma unroll
    for (int i = 0; i < 8; i++) {
        int idx = tid + i * 256, r = idx >> 4, c4 = (idx & 15) * 4;
        CP_ASYNC16(sb + (r * AP + c4) * 4, qb + r * HD + c4);
    }
#pragma unroll
    for (int i = 0; i < 4; i++) {
        int idx = tid + i * 256, r = idx >> 4, c4 = (idx & 15) * 4;
        CP_ASYNC16(sb + (ATTN_K0 + r * AP + c4) * 4, kb + r * HD + c4);
        CP_ASYNC16(sb + (ATTN_V0 + r * AP + c4) * 4, vtb + r * SEQ + c4);
    }
    CP_COMMIT();

    const uint32_t laneQ = ((lane & 15) * AP + ((lane >> 4) << 2)) * 4;
    const uint32_t laneP8 = (((lane & 7) + ((lane & 16) ? 8 : 0)) * AP +
                             ((lane & 8) ? 4 : 0)) * 4;
    const uint32_t qBase = wq * 16 * AP * 4 + laneQ;
    uint32_t pPair[4];
#pragma unroll
    for (int p = 0; p < 4; p++) pPair[p] = p * 16 * AP * 4 + laneP8;

    float m_run[2] = {-1e30f, -1e30f};
    float l_run[2] = {0.f, 0.f};
    float oAcc[8][4];
#pragma unroll
    for (int nf = 0; nf < 8; nf++)
#pragma unroll
        for (int e = 0; e < 4; e++) oAcc[nf][e] = 0.f;

    const int lr = lane >> 2, lc = lane & 3;

#pragma unroll 1
    for (int kt = 0; kt < ntiles; kt++) {
        CP_WAIT(0);
        __syncthreads();
        if (kt + 1 < ntiles) {
            const int nb = (kt + 1) & 1;
#pragma unroll
            for (int i = 0; i < 4; i++) {
                int idx = tid + i * 256, r = idx >> 4, c4 = (idx & 15) * 4;
                CP_ASYNC16(sb + (ATTN_K0 + nb * 4352 + r * AP + c4) * 4,
                           kb + ((kt + 1) * 64 + r) * HD + c4);
                CP_ASYNC16(sb + (ATTN_V0 + nb * 4352 + r * AP + c4) * 4,
                           vtb + r * SEQ + (kt + 1) * 64 + c4);
            }
            CP_COMMIT();
        }

        const uint32_t kBuf = (ATTN_K0 + (kt & 1) * 4352) * 4;
        const uint32_t vBuf = (ATTN_V0 + (kt & 1) * 4352) * 4;

        // ---- S = Q K^T (Q pre-scaled by 1/8) ----
        float sAcc[8][4];
#pragma unroll
        for (int nf = 0; nf < 8; nf++)
#pragma unroll
            for (int e = 0; e < 4; e++) sAcc[nf][e] = 0.f;

#pragma unroll
        for (int kk = 0; kk < 64; kk += 8) {
            uint32_t a0, a1, a2, a3, kf[4][4];
            LDSM_X4(a0, a1, a2, a3, sb + qBase + kk * 4);
#pragma unroll
            for (int p = 0; p < 4; p++)
                LDSM_X4(kf[p][0], kf[p][1], kf[p][2], kf[p][3],
                        sb + kBuf + pPair[p] + kk * 4);
#pragma unroll
            for (int nf = 0; nf < 8; nf++)
                mma_tf32(sAcc[nf][0], sAcc[nf][1], sAcc[nf][2], sAcc[nf][3],
                         a0, a1, a2, a3,
                         kf[nf >> 1][(nf & 1) * 2], kf[nf >> 1][(nf & 1) * 2 + 1]);
        }

        // ---- mask (last tile only) ----
        if (kt == ntiles - 1 && (vlen & 63)) {
#pragma unroll
            for (int nf = 0; nf < 8; nf++) {
#pragma unroll
                for (int e = 0; e < 2; e++) {
                    int col = kt * 64 + nf * 8 + 2 * lc + e;
                    if (col >= vlen) { sAcc[nf][e] = -1e6f; sAcc[nf][2 + e] = -1e6f; }
                }
            }
        }

        // ---- fragment online softmax ----
        float rmax0 = -1e30f, rmax1 = -1e30f;
#pragma unroll
        for (int nf = 0; nf < 8; nf++) {
            rmax0 = fmaxf(rmax0, fmaxf(sAcc[nf][0], sAcc[nf][1]));
            rmax1 = fmaxf(rmax1, fmaxf(sAcc[nf][2], sAcc[nf][3]));
        }
        rmax0 = fmaxf(rmax0, __shfl_xor_sync(0xffffffffu, rmax0, 1));
        rmax0 = fmaxf(rmax0, __shfl_xor_sync(0xffffffffu, rmax0, 2));
        rmax1 = fmaxf(rmax1, __shfl_xor_sync(0xffffffffu, rmax1, 1));
        rmax1 = fmaxf(rmax1, __shfl_xor_sync(0xffffffffu, rmax1, 2));

        float nm0 = fmaxf(m_run[0], rmax0), nm1 = fmaxf(m_run[1], rmax1);
        float alpha0 = __expf(m_run[0] - nm0), alpha1 = __expf(m_run[1] - nm1);
        m_run[0] = nm0; m_run[1] = nm1;

        float ts0 = 0.f, ts1 = 0.f;
#pragma unroll
        for (int nf = 0; nf < 8; nf++) {
#pragma unroll
            for (int e = 0; e < 2; e++) {
                float p0 = __expf(sAcc[nf][e] - nm0);
                float p1 = __expf(sAcc[nf][2 + e] - nm1);
                ts0 += p0; ts1 += p1;
                sAcc[nf][e] = p0; sAcc[nf][2 + e] = p1;
            }
        }
        ts0 += __shfl_xor_sync(0xffffffffu, ts0, 1);
        ts0 += __shfl_xor_sync(0xffffffffu, ts0, 2);
        ts1 += __shfl_xor_sync(0xffffffffu, ts1, 1);
        ts1 += __shfl_xor_sync(0xffffffffu, ts1, 2);
        l_run[0] = l_run[0] * alpha0 + ts0;
        l_run[1] = l_run[1] * alpha1 + ts1;

#pragma unroll
        for (int nf = 0; nf < 8; nf++) {
            oAcc[nf][0] *= alpha0; oAcc[nf][1] *= alpha0;
            oAcc[nf][2] *= alpha1; oAcc[nf][3] *= alpha1;
        }

        // ---- O += P V : P acc-frag -> A-frag via quad shfl ----
        const int srcA = (lane & ~3) | (lc >> 1);
        const int srcB = srcA + 2;
        const bool oddc = lc & 1;
#pragma unroll
        for (int kc = 0; kc < 8; kc++) {
            float v0 = __shfl_sync(0xffffffffu, sAcc[kc][0], srcA);
            float v1 = __shfl_sync(0xffffffffu, sAcc[kc][1], srcA);
            float v2 = __shfl_sync(0xffffffffu, sAcc[kc][2], srcA);
            float v3 = __shfl_sync(0xffffffffu, sAcc[kc][3], srcA);
            float u0 = __shfl_sync(0xffffffffu, sAcc[kc][0], srcB);
            float u1 = __shfl_sync(0xffffffffu, sAcc[kc][1], srcB);
            float u2 = __shfl_sync(0xffffffffu, sAcc[kc][2], srcB);
            float u3 = __shfl_sync(0xffffffffu, sAcc[kc][3], srcB);
            uint32_t a0 = __float_as_uint(oddc ? v1 : v0);
            uint32_t a1 = __float_as_uint(oddc ? v3 : v2);
            uint32_t a2 = __float_as_uint(oddc ? u1 : u0);
            uint32_t a3 = __float_as_uint(oddc ? u3 : u2);
            uint32_t vf[4][4];
#pragma unroll
            for (int p = 0; p < 4; p++)
                LDSM_X4(vf[p][0], vf[p][1], vf[p][2], vf[p][3],
                        sb + vBuf + pPair[p] + kc * 32);
#pragma unroll
            for (int nf = 0; nf < 8; nf++)
                mma_tf32(oAcc[nf][0], oAcc[nf][1], oAcc[nf][2], oAcc[nf][3],
                         a0, a1, a2, a3,
                         vf[nf >> 1][(nf & 1) * 2], vf[nf >> 1][(nf & 1) * 2 + 1]);
        }
    }

    // ---- epilogue ----
    float inv0 = 1.f / l_run[0], inv1 = 1.f / l_run[1];
    int row0 = qt * 128 + wq * 16 + lr;
    int row1 = row0 + 8;
#pragma unroll
    for (int nf = 0; nf < 8; nf++) {
        int col = h * HD + nf * 8 + 2 * lc;
        float2 lo = make_float2(f_rna_tf32(oAcc[nf][0] * inv0), f_rna_tf32(oAcc[nf][1] * inv0));
        float2 hi = make_float2(f_rna_tf32(oAcc[nf][2] * inv1), f_rna_tf32(oAcc[nf][3] * inv1));
        *(float2*)&g_ctx[(b * SEQ + row0) * DIM + col] = lo;
        *(float2*)&g_ctx[(b * SEQ + row1) * DIM + col] = hi;
    }
}

// ---------------------------------------------------------------------------
extern "C" void kernel_launch(void* const* d_in, const int* in_sizes, int n_in,
                              void* d_out, int out_size)
{
    const float* queries = (const float*)d_in[0];
    const float* keys    = (const float*)d_in[1];
    const float* values  = (const float*)d_in[2];
    const int*   vlens   = (const int*)d_in[3];
    const float* W_q     = (const float*)d_in[4];
    const float* W_o     = (const float*)d_in[5];
    float* out = (float*)d_out;

    cudaFuncSetAttribute(gemm_mma<0>, cudaFuncAttributeMaxDynamicSharedMemorySize, GEMM_SMEM_BYTES);
    cudaFuncSetAttribute(gemm_mma<1>, cudaFuncAttributeMaxDynamicSharedMemorySize, GEMM_SMEM_BYTES);
    cudaFuncSetAttribute(attn_tc, cudaFuncAttributeMaxDynamicSharedMemorySize, ATTN_SMEM_BYTES);

    prep_wt<<<dim3(32, 32, 2), 256>>>(W_q, W_o);
    gemm_mma<0><<<dim3(8, 32, 3), 256, GEMM_SMEM_BYTES>>>(queries, keys, values, nullptr, vlens);
    attn_tc<<<dim3(SEQ / 128, NH, BATCH), 256, ATTN_SMEM_BYTES>>>(vlens);
    gemm_mma<1><<<dim3(8, 32, 1), 256, GEMM_SMEM_BYTES>>>(nullptr, nullptr, nullptr, out, vlens);
}

// round 17
// speedup vs baseline: 1.5288x; 1.3192x over previous
#include <cuda_runtime.h>
#include <cuda_fp16.h>
#include <cstdint>

#define BATCH 4
#define SEQ   1024
#define DIM   1024
#define NH    16
#define HD    64

// -------------------- device scratch (allocation-free) ----------------------
__device__ float  g_q[BATCH * NH * SEQ * HD];    // head-split, tf32-rounded, pre-scaled 1/8
__device__ float  g_k[BATCH * NH * SEQ * HD];
__device__ float  g_vt[BATCH * NH * HD * SEQ];   // V proj, transposed [b,h,d,s]
__device__ __half g_ctx[BATCH * SEQ * DIM];      // attn output (fp16)
__device__ __half g_qh[BATCH * SEQ * DIM];       // fp16 inputs
__device__ __half g_kh[BATCH * SEQ * DIM];
__device__ __half g_vh[BATCH * SEQ * DIM];
__device__ __half g_wqth[DIM * DIM];             // W_q^T fp16, [n][k]
__device__ __half g_woth[DIM * DIM];             // W_o^T fp16, [n][k]

// -------------------- helpers ----------------------------------------------
__device__ __forceinline__ uint32_t smem_u32(const void* p) {
    uint32_t a;
    asm("{ .reg .u64 t; cvta.to.shared.u64 t, %1; cvt.u32.u64 %0, t; }" : "=r"(a) : "l"(p));
    return a;
}
__device__ __forceinline__ float f_rna_tf32(float f) {
    uint32_t r; asm("cvt.rna.tf32.f32 %0, %1;" : "=r"(r) : "f"(f));
    return __uint_as_float(r);
}

#define CP_ASYNC16(sa, gp) \
    asm volatile("cp.async.cg.shared.global [%0], [%1], 16;" :: "r"(sa), "l"(gp))
#define CP_COMMIT() asm volatile("cp.async.commit_group;" ::: "memory")
#define CP_WAIT(n)  asm volatile("cp.async.wait_group %0;" :: "n"(n) : "memory")

#define LDSM_X4(r0, r1, r2, r3, a) \
    asm volatile("ldmatrix.sync.aligned.m8n8.x4.shared.b16 {%0,%1,%2,%3}, [%4];" \
                 : "=r"(r0), "=r"(r1), "=r"(r2), "=r"(r3) : "r"(a))

__device__ __forceinline__ void mma_tf32(float& d0, float& d1, float& d2, float& d3,
                                         uint32_t a0, uint32_t a1, uint32_t a2, uint32_t a3,
                                         uint32_t b0, uint32_t b1) {
    asm volatile(
        "mma.sync.aligned.m16n8k8.row.col.f32.tf32.tf32.f32 "
        "{%0,%1,%2,%3}, {%4,%5,%6,%7}, {%8,%9}, {%0,%1,%2,%3};"
        : "+f"(d0), "+f"(d1), "+f"(d2), "+f"(d3)
        : "r"(a0), "r"(a1), "r"(a2), "r"(a3), "r"(b0), "r"(b1));
}
__device__ __forceinline__ void mma_f16(float& d0, float& d1, float& d2, float& d3,
                                        uint32_t a0, uint32_t a1, uint32_t a2, uint32_t a3,
                                        uint32_t b0, uint32_t b1) {
    asm volatile(
        "mma.sync.aligned.m16n8k16.row.col.f32.f16.f16.f32 "
        "{%0,%1,%2,%3}, {%4,%5,%6,%7}, {%8,%9}, {%0,%1,%2,%3};"
        : "+f"(d0), "+f"(d1), "+f"(d2), "+f"(d3)
        : "r"(a0), "r"(a1), "r"(a2), "r"(a3), "r"(b0), "r"(b1));
}

// -------------------- prep: fp32 -> fp16 inputs -----------------------------
__global__ void prep_h(const float* __restrict__ q, const float* __restrict__ k,
                       const float* __restrict__ v)
{
    const int y = blockIdx.y;
    const float* src = (y == 0) ? q : (y == 1) ? k : v;
    __half* dst = (y == 0) ? g_qh : (y == 1) ? g_kh : g_vh;
    const int n4 = (BATCH * SEQ * DIM) / 4;
    for (int i = blockIdx.x * blockDim.x + threadIdx.x; i < n4; i += gridDim.x * blockDim.x) {
        float4 x = ((const float4*)src)[i];
        __half2 lo = __floats2half2_rn(x.x, x.y);
        __half2 hi = __floats2half2_rn(x.z, x.w);
        uint2 o;
        o.x = *(uint32_t*)&lo;
        o.y = *(uint32_t*)&hi;
        ((uint2*)dst)[i] = o;
    }
}

// -------------------- prep: transpose + fp16 weights ------------------------
__global__ void prep_wt(const float* __restrict__ Wq, const float* __restrict__ Wo)
{
    const float* src = blockIdx.z ? Wo : Wq;
    __half* dst = blockIdx.z ? g_woth : g_wqth;
    __shared__ float t[32][33];
    const int tid = threadIdx.x;
    const int n0 = blockIdx.x * 32, k0 = blockIdx.y * 32;
#pragma unroll
    for (int i = 0; i < 4; i++) {
        int idx = tid + i * 256, r = idx >> 5, c = idx & 31;
        t[r][c] = src[(k0 + r) * DIM + n0 + c];
    }
    __syncthreads();
#pragma unroll
    for (int i = 0; i < 4; i++) {
        int idx = tid + i * 256, r = idx >> 5, c = idx & 31;
        dst[(n0 + r) * DIM + k0 + c] = __float2half_rn(t[c][r]);
    }
}

// -------------------- fp16 mma.sync GEMM (m16n8k16) -------------------------
// 128x128 tile, BK=64, 256 thr (8 warps 2x4), warp tile 64x32.
// Smem halves pitch 72 (144 B = 9x16B, odd mod 8 => LDSM conflict-free).
// 3-stage pipeline; stage = 128*144 = 18432 B; A 0..3, B at +55296.
#define PITCH_H 72
#define STAGE_B 18432
#define BOFF    55296
#define GEMM_SMEM_BYTES 110592
#define KCH 16
#define VT_PITCH 132

// MODE 0: proj (z: g_qh/g_kh/g_vh @ g_wqth). z=0 -> g_q (x1/8), z=1 -> g_k,
//         z=2 -> g_vt directly transposed. Outputs fp32 rna-rounded.
// MODE 1: out (g_ctx[fp16] @ g_woth -> outp fp32 plain)
template<int MODE>
__global__ __launch_bounds__(256, 2) void gemm_mma(
    float* __restrict__ outp, const int* __restrict__ vlens)
{
    extern __shared__ float sm[];
    const uint32_t sb = smem_u32(sm);
    const int tid = threadIdx.x, lane = tid & 31, wid = tid >> 5;
    const int wm = wid >> 2, wn = wid & 3;           // warp grid 2x4
    const int m0 = blockIdx.y * 128, n0 = blockIdx.x * 128;
    const int z = (MODE == 0) ? blockIdx.z : 0;

    const __half* A; const __half* B; float* dstF;
    if (MODE == 0) {
        A    = (z == 0) ? g_qh : (z == 1) ? g_kh : g_vh;
        dstF = (z == 0) ? g_q  : (z == 1) ? g_k  : g_vt;
        B    = g_wqth;
        if (z != 0 && (m0 & (SEQ - 1)) >= vlens[m0 >> 10]) return;
    } else {
        A = g_ctx; dstF = outp; B = g_woth;
    }

    // staging: per chunk 128 rows x 8 16B-jobs per operand, 256 thr x 4
    uint32_t saA[4], saB[4];
    const __half* gpA[4]; const __half* gpB[4];
#pragma unroll
    for (int i = 0; i < 4; i++) {
        int s = tid + i * 256;
        int r = s >> 3, c = s & 7;
        saA[i] = sb + r * 144 + c * 16;
        saB[i] = sb + BOFF + r * 144 + c * 16;
        gpA[i] = A + (m0 + r) * DIM + c * 8;
        gpB[i] = B + (n0 + r) * DIM + c * 8;
    }

    // ldmatrix lane base (bytes): rows (lane&15), +16B for upper half-k
    const uint32_t laneH = (lane & 15) * 144 + ((lane >> 4) & 1) * 16;
    uint32_t aBase[4], bBase[2];
#pragma unroll
    for (int mf = 0; mf < 4; mf++) aBase[mf] = (wm * 64 + mf * 16) * 144 + laneH;
#pragma unroll
    for (int p = 0; p < 2; p++)
        bBase[p] = BOFF + (wn * 32 + p * 16) * 144 + laneH;

    float acc[4][4][4];
#pragma unroll
    for (int mf = 0; mf < 4; mf++)
#pragma unroll
        for (int nf = 0; nf < 4; nf++)
#pragma unroll
            for (int e = 0; e < 4; e++) acc[mf][nf][e] = 0.f;

    // prologue: stage chunks 0,1
#pragma unroll
    for (int i = 0; i < 4; i++) CP_ASYNC16(saA[i], gpA[i]);
#pragma unroll
    for (int i = 0; i < 4; i++) CP_ASYNC16(saB[i], gpB[i]);
    CP_COMMIT();
#pragma unroll
    for (int i = 0; i < 4; i++) CP_ASYNC16(saA[i] + STAGE_B, gpA[i] + 64);
#pragma unroll
    for (int i = 0; i < 4; i++) CP_ASYNC16(saB[i] + STAGE_B, gpB[i] + 64);
    CP_COMMIT();

#pragma unroll 1
    for (int t = 0; t < KCH; t++) {
        if (t == KCH - 1) { CP_WAIT(0); } else { CP_WAIT(1); }
        __syncthreads();
        if (t + 2 < KCH) {
            const uint32_t d = ((t + 2) % 3) * STAGE_B;
#pragma unroll
            for (int i = 0; i < 4; i++) CP_ASYNC16(saA[i] + d, gpA[i] + (t + 2) * 64);
#pragma unroll
            for (int i = 0; i < 4; i++) CP_ASYNC16(saB[i] + d, gpB[i] + (t + 2) * 64);
            CP_COMMIT();
        }

        const uint32_t bufOff = (t % 3) * STAGE_B;
#pragma unroll
        for (int kk = 0; kk < 64; kk += 16) {
            uint32_t a[4][4], bf[2][4];
#pragma unroll
            for (int mf = 0; mf < 4; mf++)
                LDSM_X4(a[mf][0], a[mf][1], a[mf][2], a[mf][3],
                        sb + bufOff + aBase[mf] + kk * 2);
#pragma unroll
            for (int p = 0; p < 2; p++)
                LDSM_X4(bf[p][0], bf[p][1], bf[p][2], bf[p][3],
                        sb + bufOff + bBase[p] + kk * 2);
            // bf[p] = { b0(n-grp 2p), b0(2p+1), b1(2p), b1(2p+1) }
#pragma unroll
            for (int mf = 0; mf < 4; mf++)
#pragma unroll
                for (int nf = 0; nf < 4; nf++)
                    mma_f16(acc[mf][nf][0], acc[mf][nf][1], acc[mf][nf][2], acc[mf][nf][3],
                            a[mf][0], a[mf][1], a[mf][2], a[mf][3],
                            bf[nf >> 1][nf & 1], bf[nf >> 1][2 + (nf & 1)]);
        }
    }

    const int ar = lane >> 2, ac = lane & 3;

    if (MODE == 0 && z == 2) {
        // ---- transposed epilogue: acc -> smem [n][m] -> g_vt coalesced ----
        __syncthreads();   // operand buffers dead; reuse as scratch
#pragma unroll
        for (int mf = 0; mf < 4; mf++) {
#pragma unroll
            for (int nf = 0; nf < 4; nf++) {
                int ml = wm * 64 + mf * 16 + ar;
                int nl = wn * 32 + nf * 8 + ac * 2;
                sm[nl * VT_PITCH + ml]           = f_rna_tf32(acc[mf][nf][0]);
                sm[(nl + 1) * VT_PITCH + ml]     = f_rna_tf32(acc[mf][nf][1]);
                sm[nl * VT_PITCH + ml + 8]       = f_rna_tf32(acc[mf][nf][2]);
                sm[(nl + 1) * VT_PITCH + ml + 8] = f_rna_tf32(acc[mf][nf][3]);
            }
        }
        __syncthreads();
        const int bb = m0 >> 10;
        const int s0base = m0 & (SEQ - 1);
#pragma unroll
        for (int i = 0; i < 16; i++) {
            int idx = tid + i * 256;
            int r = idx >> 5, c4 = (idx & 31) * 4;
            int ng = n0 + r;
            int h = ng >> 6, dd = ng & 63;
            float4 v;
            v.x = sm[r * VT_PITCH + c4];     v.y = sm[r * VT_PITCH + c4 + 1];
            v.z = sm[r * VT_PITCH + c4 + 2]; v.w = sm[r * VT_PITCH + c4 + 3];
            *(float4*)&dstF[(((size_t)(bb * NH + h) * HD) + dd) * SEQ + s0base + c4] = v;
        }
        return;
    }

    const float qs = (MODE == 0 && z == 0) ? 0.125f : 1.0f;
#pragma unroll
    for (int mf = 0; mf < 4; mf++) {
#pragma unroll
        for (int nf = 0; nf < 4; nf++) {
            int m = m0 + wm * 64 + mf * 16 + ar;
            int n = n0 + wn * 32 + nf * 8 + ac * 2;
            if (MODE == 0) {
                float2 lo = make_float2(f_rna_tf32(acc[mf][nf][0] * qs),
                                        f_rna_tf32(acc[mf][nf][1] * qs));
                float2 hi = make_float2(f_rna_tf32(acc[mf][nf][2] * qs),
                                        f_rna_tf32(acc[mf][nf][3] * qs));
                int h = n >> 6, dd = n & 63;
                int bb0 = m >> 10, s0 = m & 1023;
                int bb1 = (m + 8) >> 10, s1 = (m + 8) & 1023;
                *(float2*)&dstF[(((bb0 * NH + h) * SEQ) + s0) * HD + dd] = lo;
                *(float2*)&dstF[(((bb1 * NH + h) * SEQ) + s1) * HD + dd] = hi;
            } else {
                *(float2*)&dstF[m * DIM + n] =
                    make_float2(acc[mf][nf][0], acc[mf][nf][1]);
                *(float2*)&dstF[(m + 8) * DIM + n] =
                    make_float2(acc[mf][nf][2], acc[mf][nf][3]);
            }
        }
    }
}

// -------------------- tensor-core flash attention (tf32, unchanged) ---------
// 128 q-rows, 8 warps, 104448 B smem => 2 CTA/SM. Heavy-batch-first.
// P fed raw fp32 (implicit tf32 truncation). Epilogue writes fp16 ctx.
#define AP 68
#define ATTN_K0 8704
#define ATTN_V0 17408
#define ATTN_SMEM_BYTES (26112 * 4)

__global__ __launch_bounds__(256) void attn_tc(const int* __restrict__ vlens)
{
    extern __shared__ float sm[];
    const uint32_t sb = smem_u32(sm);
    const int tid = threadIdx.x, lane = tid & 31, wq = tid >> 5;
    const int qt = blockIdx.x, h = blockIdx.y;

    int vb[4] = {vlens[0], vlens[1], vlens[2], vlens[3]};
    int b = 0;
#pragma unroll
    for (int i = 0; i < 4; i++) {
        int rank = 0;
#pragma unroll
        for (int j = 0; j < 4; j++)
            rank += (vb[j] > vb[i]) || (vb[j] == vb[i] && j < i);
        if (rank == (int)blockIdx.z) b = i;
    }
    const int vlen = vb[b];
    const int ntiles = (vlen + 63) >> 6;

    const float* qb  = g_q  + ((size_t)(b * NH + h) * SEQ + qt * 128) * HD;
    const float* kb  = g_k  + ((size_t)(b * NH + h) * SEQ) * HD;
    const float* vtb = g_vt + ((size_t)(b * NH + h) * HD) * SEQ;

#pragma unroll
    for (int i = 0; i < 8; i++) {
        int idx = tid + i * 256, r = idx >> 4, c4 = (idx & 15) * 4;
        CP_ASYNC16(sb + (r * AP + c4) * 4, qb + r * HD + c4);
    }
#pragma unroll
    for (int i = 0; i < 4; i++) {
        int idx = tid + i * 256, r = idx >> 4, c4 = (idx & 15) * 4;
        CP_ASYNC16(sb + (ATTN_K0 + r * AP + c4) * 4, kb + r * HD + c4);
        CP_ASYNC16(sb + (ATTN_V0 + r * AP + c4) * 4, vtb + r * SEQ + c4);
    }
    CP_COMMIT();

    const uint32_t laneQ = ((lane & 15) * AP + ((lane >> 4) << 2)) * 4;
    const uint32_t laneP8 = (((lane & 7) + ((lane & 16) ? 8 : 0)) * AP +
                             ((lane & 8) ? 4 : 0)) * 4;
    const uint32_t qBase = wq * 16 * AP * 4 + laneQ;
    uint32_t pPair[4];
#pragma unroll
    for (int p = 0; p < 4; p++) pPair[p] = p * 16 * AP * 4 + laneP8;

    float m_run[2] = {-1e30f, -1e30f};
    float l_run[2] = {0.f, 0.f};
    float oAcc[8][4];
#pragma unroll
    for (int nf = 0; nf < 8; nf++)
#pragma unroll
        for (int e = 0; e < 4; e++) oAcc[nf][e] = 0.f;

    const int lr = lane >> 2, lc = lane & 3;

#pragma unroll 1
    for (int kt = 0; kt < ntiles; kt++) {
        CP_WAIT(0);
        __syncthreads();
        if (kt + 1 < ntiles) {
            const int nb = (kt + 1) & 1;
#pragma unroll
            for (int i = 0; i < 4; i++) {
                int idx = tid + i * 256, r = idx >> 4, c4 = (idx & 15) * 4;
                CP_ASYNC16(sb + (ATTN_K0 + nb * 4352 + r * AP + c4) * 4,
                           kb + ((kt + 1) * 64 + r) * HD + c4);
                CP_ASYNC16(sb + (ATTN_V0 + nb * 4352 + r * AP + c4) * 4,
                           vtb + r * SEQ + (kt + 1) * 64 + c4);
            }
            CP_COMMIT();
        }

        const uint32_t kBuf = (ATTN_K0 + (kt & 1) * 4352) * 4;
        const uint32_t vBuf = (ATTN_V0 + (kt & 1) * 4352) * 4;

        float sAcc[8][4];
#pragma unroll
        for (int nf = 0; nf < 8; nf++)
#pragma unroll
            for (int e = 0; e < 4; e++) sAcc[nf][e] = 0.f;

#pragma unroll
        for (int kk = 0; kk < 64; kk += 8) {
            uint32_t a0, a1, a2, a3, kf[4][4];
            LDSM_X4(a0, a1, a2, a3, sb + qBase + kk * 4);
#pragma unroll
            for (int p = 0; p < 4; p++)
                LDSM_X4(kf[p][0], kf[p][1], kf[p][2], kf[p][3],
                        sb + kBuf + pPair[p] + kk * 4);
#pragma unroll
            for (int nf = 0; nf < 8; nf++)
                mma_tf32(sAcc[nf][0], sAcc[nf][1], sAcc[nf][2], sAcc[nf][3],
                         a0, a1, a2, a3,
                         kf[nf >> 1][(nf & 1) * 2], kf[nf >> 1][(nf & 1) * 2 + 1]);
        }

        if (kt == ntiles - 1 && (vlen & 63)) {
#pragma unroll
            for (int nf = 0; nf < 8; nf++) {
#pragma unroll
                for (int e = 0; e < 2; e++) {
                    int col = kt * 64 + nf * 8 + 2 * lc + e;
                    if (col >= vlen) { sAcc[nf][e] = -1e6f; sAcc[nf][2 + e] = -1e6f; }
                }
            }
        }

        float rmax0 = -1e30f, rmax1 = -1e30f;
#pragma unroll
        for (int nf = 0; nf < 8; nf++) {
            rmax0 = fmaxf(rmax0, fmaxf(sAcc[nf][0], sAcc[nf][1]));
            rmax1 = fmaxf(rmax1, fmaxf(sAcc[nf][2], sAcc[nf][3]));
        }
        rmax0 = fmaxf(rmax0, __shfl_xor_sync(0xffffffffu, rmax0, 1));
        rmax0 = fmaxf(rmax0, __shfl_xor_sync(0xffffffffu, rmax0, 2));
        rmax1 = fmaxf(rmax1, __shfl_xor_sync(0xffffffffu, rmax1, 1));
        rmax1 = fmaxf(rmax1, __shfl_xor_sync(0xffffffffu, rmax1, 2));

        float nm0 = fmaxf(m_run[0], rmax0), nm1 = fmaxf(m_run[1], rmax1);
        float alpha0 = __expf(m_run[0] - nm0), alpha1 = __expf(m_run[1] - nm1);
        m_run[0] = nm0; m_run[1] = nm1;

        float ts0 = 0.f, ts1 = 0.f;
#pragma unroll
        for (int nf = 0; nf < 8; nf++) {
#pragma unroll
            for (int e = 0; e < 2; e++) {
                float p0 = __expf(sAcc[nf][e] - nm0);
                float p1 = __expf(sAcc[nf][2 + e] - nm1);
                ts0 += p0; ts1 += p1;
                sAcc[nf][e] = p0; sAcc[nf][2 + e] = p1;
            }
        }
        ts0 += __shfl_xor_sync(0xffffffffu, ts0, 1);
        ts0 += __shfl_xor_sync(0xffffffffu, ts0, 2);
        ts1 += __shfl_xor_sync(0xffffffffu, ts1, 1);
        ts1 += __shfl_xor_sync(0xffffffffu, ts1, 2);
        l_run[0] = l_run[0] * alpha0 + ts0;
        l_run[1] = l_run[1] * alpha1 + ts1;

#pragma unroll
        for (int nf = 0; nf < 8; nf++) {
            oAcc[nf][0] *= alpha0; oAcc[nf][1] *= alpha0;
            oAcc[nf][2] *= alpha1; oAcc[nf][3] *= alpha1;
        }

        const int srcA = (lane & ~3) | (lc >> 1);
        const int srcB = srcA + 2;
        const bool oddc = lc & 1;
#pragma unroll
        for (int kc = 0; kc < 8; kc++) {
            float v0 = __shfl_sync(0xffffffffu, sAcc[kc][0], srcA);
            float v1 = __shfl_sync(0xffffffffu, sAcc[kc][1], srcA);
            float v2 = __shfl_sync(0xffffffffu, sAcc[kc][2], srcA);
            float v3 = __shfl_sync(0xffffffffu, sAcc[kc][3], srcA);
            float u0 = __shfl_sync(0xffffffffu, sAcc[kc][0], srcB);
            float u1 = __shfl_sync(0xffffffffu, sAcc[kc][1], srcB);
            float u2 = __shfl_sync(0xffffffffu, sAcc[kc][2], srcB);
            float u3 = __shfl_sync(0xffffffffu, sAcc[kc][3], srcB);
            uint32_t a0 = __float_as_uint(oddc ? v1 : v0);
            uint32_t a1 = __float_as_uint(oddc ? v3 : v2);
            uint32_t a2 = __float_as_uint(oddc ? u1 : u0);
            uint32_t a3 = __float_as_uint(oddc ? u3 : u2);
            uint32_t vf[4][4];
#pragma unroll
            for (int p = 0; p < 4; p++)
                LDSM_X4(vf[p][0], vf[p][1], vf[p][2], vf[p][3],
                        sb + vBuf + pPair[p] + kc * 32);
#pragma unroll
            for (int nf = 0; nf < 8; nf++)
                mma_tf32(oAcc[nf][0], oAcc[nf][1], oAcc[nf][2], oAcc[nf][3],
                         a0, a1, a2, a3,
                         vf[nf >> 1][(nf & 1) * 2], vf[nf >> 1][(nf & 1) * 2 + 1]);
        }
    }

    // ---- epilogue: normalize, store ctx as fp16 ----
    float inv0 = 1.f / l_run[0], inv1 = 1.f / l_run[1];
    int row0 = qt * 128 + wq * 16 + lr;
    int row1 = row0 + 8;
#pragma unroll
    for (int nf = 0; nf < 8; nf++) {
        int col = h * HD + nf * 8 + 2 * lc;
        __half2 lo = __floats2half2_rn(oAcc[nf][0] * inv0, oAcc[nf][1] * inv0);
        __half2 hi = __floats2half2_rn(oAcc[nf][2] * inv1, oAcc[nf][3] * inv1);
        *(__half2*)&g_ctx[(b * SEQ + row0) * DIM + col] = lo;
        *(__half2*)&g_ctx[(b * SEQ + row1) * DIM + col] = hi;
    }
}

// ---------------------------------------------------------------------------
extern "C" void kernel_launch(void* const* d_in, const int* in_sizes, int n_in,
                              void* d_out, int out_size)
{
    const float* queries = (const float*)d_in[0];
    const float* keys    = (const float*)d_in[1];
    const float* values  = (const float*)d_in[2];
    const int*   vlens   = (const int*)d_in[3];
    const float* W_q     = (const float*)d_in[4];
    const float* W_o     = (const float*)d_in[5];
    float* out = (float*)d_out;

    cudaFuncSetAttribute(gemm_mma<0>, cudaFuncAttributeMaxDynamicSharedMemorySize, GEMM_SMEM_BYTES);
    cudaFuncSetAttribute(gemm_mma<1>, cudaFuncAttributeMaxDynamicSharedMemorySize, GEMM_SMEM_BYTES);
    cudaFuncSetAttribute(attn_tc, cudaFuncAttributeMaxDynamicSharedMemorySize, ATTN_SMEM_BYTES);

    prep_h<<<dim3(512, 3), 256>>>(queries, keys, values);
    prep_wt<<<dim3(32, 32, 2), 256>>>(W_q, W_o);
    gemm_mma<0><<<dim3(8, 32, 3), 256, GEMM_SMEM_BYTES>>>(nullptr, vlens);
    attn_tc<<<dim3(SEQ / 128, NH, BATCH), 256, ATTN_SMEM_BYTES>>>(vlens);
    gemm_mma<1><<<dim3(8, 32, 1), 256, GEMM_SMEM_BYTES>>>(out, vlens);
}